// round 2
// baseline (speedup 1.0000x reference)
#include <cuda_runtime.h>
#include <cstddef>

#define Bn 32
#define Tn 256
#define Wn 128
#define Rn 4
#define Nn 128
#define IFACEn 919
#define INSZn 640
#define Gn 512
#define NTH 512
#define NWARP 16
#define DELTAf 1e-6f

struct Smem {
    float mem[Nn][Wn];     // 16384
    float lnk[Nn][Nn];     // 16384
    float h_enc[Wn], c_enc[Wn];
    float h_ctl[Wn], c_ctl[Wn];
    float rv[Wn][Rn];      // read vectors [w][r]  (flat = w*4+r, matches reshape)
    float rw[Rn][Nn];      // previous read weights
    float rwn[Rn][Nn];     // new read weights
    float ww[Nn];
    float prec[Nn];
    float usage[Nn];
    float xt[Wn];
    float ge[Gn];
    float xc[INSZn];
    float xi[IFACEn + 1];
    float rk[Rn][Wn];
    float wk[Wn];
    float er[Wn];
    float wv[Wn];
    float rstr[Rn];
    float fg[Rn];
    float rknorm[Rn];
    float rm[Rn][3];       // 12 floats, keeps 16B alignment
    float wc[Nn];
    float uu[Nn];
    float psu[Nn];
    float alloc_[Nn];
    float nrm[Nn];
    float rc[Rn][Nn];
    float fwv[Rn][Nn];
    float bwv[Rn][Nn];
    float xout[INSZn];
    float red[NWARP];
    float segred[Rn];
    float scal[8];         // 0:write_str 1:alloc_gate 2:write_gate 3:wknorm 4:max 5:invsum 6:sum_ww
    int   rnk[Nn];
};

__device__ __forceinline__ float sigm(float x) { return 1.0f / (1.0f + expf(-x)); }
__device__ __forceinline__ float softplusf(float x) {
    return (x > 0.f) ? (x + log1pf(expf(-x))) : log1pf(expf(x));
}
__device__ __forceinline__ float wsum(float v) {
    v += __shfl_xor_sync(0xffffffffu, v, 16);
    v += __shfl_xor_sync(0xffffffffu, v, 8);
    v += __shfl_xor_sync(0xffffffffu, v, 4);
    v += __shfl_xor_sync(0xffffffffu, v, 2);
    v += __shfl_xor_sync(0xffffffffu, v, 1);
    return v;
}
__device__ __forceinline__ float wmax(float v) {
    v = fmaxf(v, __shfl_xor_sync(0xffffffffu, v, 16));
    v = fmaxf(v, __shfl_xor_sync(0xffffffffu, v, 8));
    v = fmaxf(v, __shfl_xor_sync(0xffffffffu, v, 4));
    v = fmaxf(v, __shfl_xor_sync(0xffffffffu, v, 2));
    v = fmaxf(v, __shfl_xor_sync(0xffffffffu, v, 1));
    return v;
}
__device__ __forceinline__ float dot4(float4 a, float4 b) {
    return a.x * b.x + a.y * b.y + a.z * b.z + a.w * b.w;
}

__global__ void __launch_bounds__(NTH, 1) dnc_kernel(
    const float* __restrict__ input,
    const float* __restrict__ enc_Wih, const float* __restrict__ enc_Whh,
    const float* __restrict__ enc_bih, const float* __restrict__ enc_bhh,
    const float* __restrict__ ctl_Wih, const float* __restrict__ ctl_Whh,
    const float* __restrict__ ctl_bih, const float* __restrict__ ctl_bhh,
    const float* __restrict__ iface_W, const float* __restrict__ iface_b,
    const float* __restrict__ out_W, const float* __restrict__ out_b,
    float* __restrict__ out)
{
    extern __shared__ char smraw[];
    Smem* s = reinterpret_cast<Smem*>(smraw);
    const int b = blockIdx.x;
    const int tid = threadIdx.x;
    const int wid = tid >> 5;
    const int lane = tid & 31;

    // ---- zero all recurrent state ----
    {
        float* p = &s->mem[0][0];   // mem + lnk contiguous
        for (int i = tid; i < Nn * Wn + Nn * Nn; i += NTH) p[i] = 0.f;
        if (tid < Wn) {
            s->h_enc[tid] = 0.f; s->c_enc[tid] = 0.f;
            s->h_ctl[tid] = 0.f; s->c_ctl[tid] = 0.f;
            s->ww[tid] = 0.f; s->prec[tid] = 0.f; s->usage[tid] = 0.f;
        }
        ((float*)s->rw)[tid] = 0.f;
        ((float*)s->rv)[tid] = 0.f;
    }
    __syncthreads();

    for (int t = 0; t < Tn; ++t) {
        // ================= encoder LSTM step =================
        if (tid < Wn) s->xt[tid] = input[((size_t)b * Tn + t) * Wn + tid];
        __syncthreads();
        {
            const float4* xs = (const float4*)s->xt;
            const float4* hs = (const float4*)s->h_enc;
            float4 x4 = xs[lane];
            float4 h4 = hs[lane];
            for (int rr = 0; rr < 32; ++rr) {
                int j = wid * 32 + rr;
                float4 a = ((const float4*)(enc_Wih + (size_t)j * Wn))[lane];
                float4 c = ((const float4*)(enc_Whh + (size_t)j * Wn))[lane];
                float acc = dot4(a, x4) + dot4(c, h4);
                acc = wsum(acc);
                if (lane == 0) s->ge[j] = acc + enc_bih[j] + enc_bhh[j];
            }
        }
        __syncthreads();
        if (tid < Wn) {
            float gi = sigm(s->ge[tid]);
            float gf = sigm(s->ge[Wn + tid]);
            float gg = tanhf(s->ge[2 * Wn + tid]);
            float go = sigm(s->ge[3 * Wn + tid]);
            float c = gf * s->c_enc[tid] + gi * gg;
            s->c_enc[tid] = c;
            s->h_enc[tid] = go * tanhf(c);
        }
        __syncthreads();

        // ================= controller input (interleaved cat) =================
        if (tid < Wn) {
            s->xc[tid * 5 + 0] = s->h_enc[tid];
            s->xc[tid * 5 + 1] = s->rv[tid][0];
            s->xc[tid * 5 + 2] = s->rv[tid][1];
            s->xc[tid * 5 + 3] = s->rv[tid][2];
            s->xc[tid * 5 + 4] = s->rv[tid][3];
        }
        __syncthreads();

        // ================= controller LSTM step =================
        {
            const float4* xs = (const float4*)s->xc;
            const float4* hs = (const float4*)s->h_ctl;
            float4 h4 = hs[lane];
            for (int rr = 0; rr < 32; ++rr) {
                int j = wid * 32 + rr;
                const float4* wi = (const float4*)(ctl_Wih + (size_t)j * INSZn);
                float acc = 0.f;
#pragma unroll
                for (int k = 0; k < 5; ++k) {
                    float4 a = wi[lane + 32 * k];
                    float4 x = xs[lane + 32 * k];
                    acc += dot4(a, x);
                }
                float4 c = ((const float4*)(ctl_Whh + (size_t)j * Wn))[lane];
                acc += dot4(c, h4);
                acc = wsum(acc);
                if (lane == 0) s->ge[j] = acc + ctl_bih[j] + ctl_bhh[j];
            }
        }
        __syncthreads();
        if (tid < Wn) {
            float gi = sigm(s->ge[tid]);
            float gf = sigm(s->ge[Wn + tid]);
            float gg = tanhf(s->ge[2 * Wn + tid]);
            float go = sigm(s->ge[3 * Wn + tid]);
            float c = gf * s->c_ctl[tid] + gi * gg;
            s->c_ctl[tid] = c;
            s->h_ctl[tid] = go * tanhf(c);
        }
        __syncthreads();

        // ================= interface projection =================
        {
            const float4* hs = (const float4*)s->h_ctl;
            float4 h4 = hs[lane];
            for (int j = wid; j < IFACEn; j += NWARP) {
                float4 a = ((const float4*)(iface_W + (size_t)j * Wn))[lane];
                float acc = dot4(a, h4);
                acc = wsum(acc);
                if (lane == 0) s->xi[j] = acc + iface_b[j];
            }
        }
        __syncthreads();

        // ================= parse interface =================
        {
            for (int i = tid; i < Rn * Wn; i += NTH) ((float*)s->rk)[i] = tanhf(s->xi[i]);
            if (tid < Wn) {
                s->wk[tid] = tanhf(s->xi[516 + tid]);
                s->er[tid] = sigm(s->xi[645 + tid]);
                s->wv[tid] = tanhf(s->xi[773 + tid]);
            }
            if (tid >= 256 && tid < 256 + Rn) {
                int r = tid - 256;
                s->rstr[r] = softplusf(s->xi[512 + r]);
                s->fg[r] = sigm(s->xi[901 + r]);
                float a = s->xi[907 + r * 3], b2 = s->xi[908 + r * 3], c2 = s->xi[909 + r * 3];
                float m = fmaxf(a, fmaxf(b2, c2));
                float ea = expf(a - m), eb = expf(b2 - m), ec = expf(c2 - m);
                float inv = 1.f / (ea + eb + ec);
                s->rm[r][0] = ea * inv; s->rm[r][1] = eb * inv; s->rm[r][2] = ec * inv;
            }
            if (tid == NTH - 1) {
                s->scal[0] = softplusf(s->xi[644]);  // write_str
                s->scal[1] = sigm(s->xi[905]);       // alloc_gate
                s->scal[2] = sigm(s->xi[906]);       // write_gate
            }
        }
        __syncthreads();

        // ======== usage update (prev ww, prev rw) + wk norm + old-mem norms & wk dots ========
        if (tid < Nn) {
            float us = s->usage[tid];
            us = us + (1.f - us) * s->ww[tid];
            float ret = 1.f;
#pragma unroll
            for (int r = 0; r < Rn; ++r) ret *= (1.f - s->fg[r] * s->rw[r][tid]);
            s->usage[tid] = us * ret;
        }
        {
            float4 k4 = ((const float4*)s->wk)[lane];
            if (wid == 0) {
                float nv = wsum(dot4(k4, k4));
                if (lane == 0) s->scal[3] = sqrtf(nv);
            }
            for (int rr = 0; rr < 8; ++rr) {
                int n = wid * 8 + rr;
                float4 m4 = ((const float4*)s->mem[n])[lane];
                float dn = dot4(m4, m4);
                float dk = dot4(m4, k4);
                dn = wsum(dn); dk = wsum(dk);
                if (lane == 0) { s->nrm[n] = sqrtf(dn); s->wc[n] = dk; }
            }
        }
        __syncthreads();

        // ======== write content softmax over N ========
        {
            float v = -1e30f;
            if (tid < Nn) {
                v = s->wc[tid] / ((s->nrm[tid] + DELTAf) * (s->scal[3] + DELTAf)) * s->scal[0];
                s->wc[tid] = v;
            }
            float m = wmax(v);
            if (lane == 0) s->red[wid] = m;
            __syncthreads();
            if (tid == 0)
                s->scal[4] = fmaxf(fmaxf(s->red[0], s->red[1]), fmaxf(s->red[2], s->red[3]));
            __syncthreads();
            float e = 0.f;
            if (tid < Nn) { e = expf(s->wc[tid] - s->scal[4]); s->wc[tid] = e; }
            float sm = wsum(e);
            if (lane == 0) s->red[wid] = sm;
            __syncthreads();
            if (tid == 0) s->scal[5] = 1.f / (s->red[0] + s->red[1] + s->red[2] + s->red[3]);
            __syncthreads();
            if (tid < Nn) s->wc[tid] *= s->scal[5];
        }

        // ======== allocation weighting (stable rank + cumprod scan) ========
        if (tid < Nn) s->uu[tid] = DELTAf + (1.f - DELTAf) * s->usage[tid];
        __syncthreads();
        if (tid < Nn) {
            float un = s->uu[tid];
            int rk_ = 0;
#pragma unroll 4
            for (int j = 0; j < Nn; ++j) {
                float uj = s->uu[j];
                rk_ += (uj < un) || (uj == un && j < tid);
            }
            s->rnk[tid] = rk_;
            s->psu[rk_] = un;   // scatter into sorted order (ranks are a permutation)
        }
        __syncthreads();
        for (int off = 1; off < Nn; off <<= 1) {   // inclusive cumprod (Hillis-Steele)
            float v = 0.f;
            if (tid < Nn) { v = s->psu[tid]; if (tid >= off) v *= s->psu[tid - off]; }
            __syncthreads();
            if (tid < Nn) s->psu[tid] = v;
            __syncthreads();
        }
        if (tid < Nn) {
            int r_ = s->rnk[tid];
            float excl = (r_ == 0) ? 1.f : s->psu[r_ - 1];
            s->alloc_[tid] = (1.f - s->uu[tid]) * excl;
        }
        __syncthreads();

        // ======== new write weighting + its sum ========
        {
            float v = 0.f;
            if (tid < Nn) {
                float ag = s->scal[1], wg = s->scal[2];
                v = wg * (ag * s->alloc_[tid] + (1.f - ag) * s->wc[tid]);
                s->ww[tid] = v;
            }
            float sm = wsum(v);
            if (lane == 0) s->red[wid] = sm;
            __syncthreads();
            if (tid == 0) s->scal[6] = s->red[0] + s->red[1] + s->red[2] + s->red[3];
            __syncthreads();
        }

        // ======== memory erase+write, link update (old prec) ========
        {
            float4* m4 = (float4*)s->mem;
            const float4* e4p = (const float4*)s->er;
            const float4* v4p = (const float4*)s->wv;
#pragma unroll
            for (int it = 0; it < 8; ++it) {
                int idx = tid + it * NTH;
                int n = idx >> 5, q = idx & 31;
                float wwn = s->ww[n];
                float4 m = m4[idx], e = e4p[q], v = v4p[q];
                m.x = m.x * (1.f - wwn * e.x) + wwn * v.x;
                m.y = m.y * (1.f - wwn * e.y) + wwn * v.y;
                m.z = m.z * (1.f - wwn * e.z) + wwn * v.z;
                m.w = m.w * (1.f - wwn * e.w) + wwn * v.w;
                m4[idx] = m;
            }
            float4* l4 = (float4*)s->lnk;
            const float4* wwp = (const float4*)s->ww;
            const float4* pcp = (const float4*)s->prec;
#pragma unroll
            for (int it = 0; it < 8; ++it) {
                int idx = tid + it * NTH;
                int i = idx >> 5, q = idx & 31;
                float wwi = s->ww[i];
                float4 L = l4[idx], wj = wwp[q], pj = pcp[q];
                L.x = (1.f - wwi - wj.x) * L.x + wwi * pj.x;
                L.y = (1.f - wwi - wj.y) * L.y + wwi * pj.y;
                L.z = (1.f - wwi - wj.z) * L.z + wwi * pj.z;
                L.w = (1.f - wwi - wj.w) * L.w + wwi * pj.w;
                if ((i >> 2) == q) ((float*)&L)[i & 3] = 0.f;   // zero diagonal
                l4[idx] = L;
            }
        }
        __syncthreads();

        // ======== precedence update + new-mem norms & read-key dots ========
        if (tid < Nn) s->prec[tid] = (1.f - s->scal[6]) * s->prec[tid] + s->ww[tid];
        {
            if (wid < Rn) {
                float4 k4 = ((const float4*)s->rk[wid])[lane];
                float nv = wsum(dot4(k4, k4));
                if (lane == 0) s->rknorm[wid] = sqrtf(nv);
            }
            float4 k0 = ((const float4*)s->rk[0])[lane];
            float4 k1 = ((const float4*)s->rk[1])[lane];
            float4 k2 = ((const float4*)s->rk[2])[lane];
            float4 k3 = ((const float4*)s->rk[3])[lane];
            for (int rr = 0; rr < 8; ++rr) {
                int n = wid * 8 + rr;
                float4 m = ((const float4*)s->mem[n])[lane];
                float dn = dot4(m, m);
                float d0 = dot4(m, k0);
                float d1 = dot4(m, k1);
                float d2 = dot4(m, k2);
                float d3 = dot4(m, k3);
                dn = wsum(dn); d0 = wsum(d0); d1 = wsum(d1); d2 = wsum(d2); d3 = wsum(d3);
                if (lane == 0) {
                    s->nrm[n] = sqrtf(dn);
                    s->rc[0][n] = d0; s->rc[1][n] = d1; s->rc[2][n] = d2; s->rc[3][n] = d3;
                }
            }
        }
        __syncthreads();

        // ======== read content softmax (4 segments of 128) ========
        {
            int r_ = tid >> 7, n = tid & 127;
            float v = s->rc[r_][n] / ((s->nrm[n] + DELTAf) * (s->rknorm[r_] + DELTAf)) * s->rstr[r_];
            float m = wmax(v);
            if (lane == 0) s->red[wid] = m;
            __syncthreads();
            if (tid < Rn)
                s->segred[tid] = fmaxf(fmaxf(s->red[4 * tid], s->red[4 * tid + 1]),
                                       fmaxf(s->red[4 * tid + 2], s->red[4 * tid + 3]));
            __syncthreads();
            float e = expf(v - s->segred[r_]);
            float sm = wsum(e);
            if (lane == 0) s->red[wid] = sm;
            __syncthreads();
            if (tid < Rn)
                s->segred[tid] = 1.f / (s->red[4 * tid] + s->red[4 * tid + 1] +
                                        s->red[4 * tid + 2] + s->red[4 * tid + 3]);
            __syncthreads();
            s->rc[r_][n] = e * s->segred[r_];
        }
        __syncthreads();

        // ======== forward / backward temporal weights (new link, OLD rw) ========
        {
            // fw[r][i] = sum_j link[i][j] * rw[r][j]   (warp-cooperative, row-contiguous)
            for (int rr = 0; rr < 32; ++rr) {
                int o = wid * 32 + rr;
                int r_ = o >> 7, i = o & 127;
                float4 L = ((const float4*)s->lnk[i])[lane];
                float4 w4 = ((const float4*)s->rw[r_])[lane];
                float acc = wsum(dot4(L, w4));
                if (lane == 0) s->fwv[r_][i] = acc;
            }
            // bw[r][i] = sum_j rw[r][j] * link[j][i]   (lanes over i -> conflict-free)
            int r_ = tid >> 7, i = tid & 127;
            float acc = 0.f;
#pragma unroll 4
            for (int j = 0; j < Nn; ++j)
                acc += s->rw[r_][j] * s->lnk[j][i];
            s->bwv[r_][i] = acc;
        }
        __syncthreads();

        // ======== combine read modes ========
        {
            int r_ = tid >> 7, n = tid & 127;
            s->rwn[r_][n] = s->rm[r_][0] * s->bwv[r_][n]
                          + s->rm[r_][1] * s->fwv[r_][n]
                          + s->rm[r_][2] * s->rc[r_][n];
        }
        __syncthreads();

        // ======== read vectors rv[w][r] = sum_n rwn[r][n]*mem[n][w]; commit rw ========
        {
            int r_ = tid >> 7, w = tid & 127;
            float acc = 0.f;
#pragma unroll 4
            for (int n = 0; n < Nn; ++n)
                acc += s->rwn[r_][n] * s->mem[n][w];
            s->rv[w][r_] = acc;
            ((float*)s->rw)[tid] = ((float*)s->rwn)[tid];
        }
        __syncthreads();

        // ======== output projection ========
        if (tid < Wn) s->xout[tid] = s->h_ctl[tid];
        s->xout[Wn + tid] = ((float*)s->rv)[tid];   // rv flat is w*4+r, matches reshape
        __syncthreads();
        {
            const float4* xs = (const float4*)s->xout;
            for (int rr = 0; rr < 8; ++rr) {
                int o = wid * 8 + rr;
                const float4* wr = (const float4*)(out_W + (size_t)o * INSZn);
                float acc = 0.f;
#pragma unroll
                for (int k = 0; k < 5; ++k) {
                    float4 a = wr[lane + 32 * k];
                    float4 x = xs[lane + 32 * k];
                    acc += dot4(a, x);
                }
                acc = wsum(acc);
                if (lane == 0) out[((size_t)b * Tn + t) * Wn + o] = acc + out_b[o];
            }
        }
        __syncthreads();
    }
}

extern "C" void kernel_launch(void* const* d_in, const int* in_sizes, int n_in,
                              void* d_out, int out_size) {
    const float* input   = (const float*)d_in[0];
    // d_in[1] = source_lengths (all == T, unused)
    const float* enc_Wih = (const float*)d_in[2];
    const float* enc_Whh = (const float*)d_in[3];
    const float* enc_bih = (const float*)d_in[4];
    const float* enc_bhh = (const float*)d_in[5];
    const float* ctl_Wih = (const float*)d_in[6];
    const float* ctl_Whh = (const float*)d_in[7];
    const float* ctl_bih = (const float*)d_in[8];
    const float* ctl_bhh = (const float*)d_in[9];
    const float* iface_W = (const float*)d_in[10];
    const float* iface_b = (const float*)d_in[11];
    const float* out_W   = (const float*)d_in[12];
    const float* out_b   = (const float*)d_in[13];
    float* out = (float*)d_out;

    int smem = (int)sizeof(Smem);
    cudaFuncSetAttribute(dnc_kernel, cudaFuncAttributeMaxDynamicSharedMemorySize, smem);
    dnc_kernel<<<Bn, NTH, smem>>>(input,
                                  enc_Wih, enc_Whh, enc_bih, enc_bhh,
                                  ctl_Wih, ctl_Whh, ctl_bih, ctl_bhh,
                                  iface_W, iface_b, out_W, out_b, out);
}

// round 3
// speedup vs baseline: 2.4376x; 2.4376x over previous
#include <cuda_runtime.h>
#include <cstddef>

#define Bn 32
#define Tn 256
#define Wn 128
#define Rn 4
#define Nn 128
#define IFACEn 919
#define INSZn 640
#define NTH 512
#define NWARP 16
#define DELTAf 1e-6f

// -------- transposed-weight scratch (written once per launch by prep kernel) --------
__device__ float g_encT[256 * 512];   // [k][j]  k = x(128)||h(128), j = gate row
__device__ float g_ctlT[768 * 512];   // [k][j]  k = xc(640)||h(128)
__device__ float g_ifcT[128 * 920];   // [k][j]  j padded 919->920
__device__ float g_outT[640 * 128];   // [k][o]
__device__ float g_benc[512];
__device__ float g_bctl[512];
__device__ float g_bifc[920];
__device__ float g_bout[128];

__global__ void prep_kernel(
    const float* __restrict__ enc_Wih, const float* __restrict__ enc_Whh,
    const float* __restrict__ enc_bih, const float* __restrict__ enc_bhh,
    const float* __restrict__ ctl_Wih, const float* __restrict__ ctl_Whh,
    const float* __restrict__ ctl_bih, const float* __restrict__ ctl_bhh,
    const float* __restrict__ iface_W, const float* __restrict__ iface_b,
    const float* __restrict__ out_W, const float* __restrict__ out_b)
{
    const int idx = blockIdx.x * blockDim.x + threadIdx.x;
    const int stride = gridDim.x * blockDim.x;
    for (int i = idx; i < 256 * 512; i += stride) {
        int k = i >> 9, j = i & 511;
        g_encT[i] = (k < 128) ? enc_Wih[(size_t)j * 128 + k]
                              : enc_Whh[(size_t)j * 128 + (k - 128)];
    }
    for (int i = idx; i < 768 * 512; i += stride) {
        int k = i >> 9, j = i & 511;
        g_ctlT[i] = (k < 640) ? ctl_Wih[(size_t)j * 640 + k]
                              : ctl_Whh[(size_t)j * 128 + (k - 640)];
    }
    for (int i = idx; i < 128 * 920; i += stride) {
        int k = i / 920, j = i - k * 920;
        g_ifcT[i] = (j < IFACEn) ? iface_W[(size_t)j * 128 + k] : 0.f;
    }
    for (int i = idx; i < 640 * 128; i += stride) {
        int k = i >> 7, o = i & 127;
        g_outT[i] = out_W[(size_t)o * 640 + k];
    }
    if (idx < 512) {
        g_benc[idx] = enc_bih[idx] + enc_bhh[idx];
        g_bctl[idx] = ctl_bih[idx] + ctl_bhh[idx];
    }
    if (idx < 920) g_bifc[idx] = (idx < IFACEn) ? iface_b[idx] : 0.f;
    if (idx < 128) g_bout[idx] = out_b[idx];
}

struct Smem {
    float mem[Nn][Wn];     // 64KB
    float lnk[Nn][Nn];     // 64KB
    float gp[2048];        // GEMV partial sums (also out-proj partials)
    float xs[768];         // GEMV x vectors
    float h_enc[Wn], c_enc[Wn];
    float h_ctl[Wn], c_ctl[Wn];
    float rv[Wn][Rn];      // read vectors [w][r]  (flat = w*4+r, matches reshape)
    float rw[Rn][Nn];
    float rwn[Rn][Nn];
    float ww[Nn];
    float prec[Nn];
    float usage[Nn];
    float xi[920];
    float rk[Rn][Wn];
    float wk[Wn];
    float er[Wn];
    float wv[Wn];
    float rstr[Rn];
    float fg[Rn];
    float rknorm[Rn];
    float rm[Rn][3];
    float wc[Nn];
    float uu[Nn];
    float psu[Nn];
    float alloc_[Nn];
    float nrm[Nn];
    float rc[Rn][Nn];
    float fwv[Rn][Nn];
    float bwv[Rn][Nn];
    float red[NWARP];
    float segred[Rn];
    float scal[8];
    int   rnk[Nn];
};

__device__ __forceinline__ float sigm(float x) { return 1.0f / (1.0f + expf(-x)); }
__device__ __forceinline__ float softplusf(float x) {
    return (x > 0.f) ? (x + log1pf(expf(-x))) : log1pf(expf(x));
}
__device__ __forceinline__ float wsum(float v) {
    v += __shfl_xor_sync(0xffffffffu, v, 16);
    v += __shfl_xor_sync(0xffffffffu, v, 8);
    v += __shfl_xor_sync(0xffffffffu, v, 4);
    v += __shfl_xor_sync(0xffffffffu, v, 2);
    v += __shfl_xor_sync(0xffffffffu, v, 1);
    return v;
}
__device__ __forceinline__ float wmax(float v) {
    v = fmaxf(v, __shfl_xor_sync(0xffffffffu, v, 16));
    v = fmaxf(v, __shfl_xor_sync(0xffffffffu, v, 8));
    v = fmaxf(v, __shfl_xor_sync(0xffffffffu, v, 4));
    v = fmaxf(v, __shfl_xor_sync(0xffffffffu, v, 2));
    v = fmaxf(v, __shfl_xor_sync(0xffffffffu, v, 1));
    return v;
}
__device__ __forceinline__ float dot4(float4 a, float4 b) {
    return a.x * b.x + a.y * b.y + a.z * b.z + a.w * b.w;
}

// 4-block accumulate: xv broadcasts, 4 LDG.128 columns
#define GEMV_BLOCK(WP, ROWSTRIDE, K)                                           \
    {                                                                          \
        float4 xv = *(const float4*)&xsrc[(K)];                                \
        float4 w0 = (WP)[(size_t)((K) + 0) * (ROWSTRIDE)];                     \
        float4 w1 = (WP)[(size_t)((K) + 1) * (ROWSTRIDE)];                     \
        float4 w2 = (WP)[(size_t)((K) + 2) * (ROWSTRIDE)];                     \
        float4 w3 = (WP)[(size_t)((K) + 3) * (ROWSTRIDE)];                     \
        a0.x += xv.x * w0.x; a0.y += xv.x * w0.y; a0.z += xv.x * w0.z; a0.w += xv.x * w0.w; \
        a1.x += xv.y * w1.x; a1.y += xv.y * w1.y; a1.z += xv.y * w1.z; a1.w += xv.y * w1.w; \
        a2.x += xv.z * w2.x; a2.y += xv.z * w2.y; a2.z += xv.z * w2.z; a2.w += xv.z * w2.w; \
        a3.x += xv.w * w3.x; a3.y += xv.w * w3.y; a3.z += xv.w * w3.z; a3.w += xv.w * w3.w; \
    }

__global__ void __launch_bounds__(NTH, 1) dnc_kernel(
    const float* __restrict__ input,
    float* __restrict__ out)
{
    extern __shared__ char smraw[];
    Smem* s = reinterpret_cast<Smem*>(smraw);
    const int b = blockIdx.x;
    const int tid = threadIdx.x;
    const int wid = tid >> 5;
    const int lane = tid & 31;

    // ---- zero all recurrent state ----
    {
        float* p = &s->mem[0][0];   // mem + lnk contiguous
        for (int i = tid; i < Nn * Wn + Nn * Nn; i += NTH) p[i] = 0.f;
        if (tid < Wn) {
            s->h_enc[tid] = 0.f; s->c_enc[tid] = 0.f;
            s->h_ctl[tid] = 0.f; s->c_ctl[tid] = 0.f;
            s->ww[tid] = 0.f; s->prec[tid] = 0.f; s->usage[tid] = 0.f;
        }
        ((float*)s->rw)[tid] = 0.f;
        ((float*)s->rv)[tid] = 0.f;
    }
    __syncthreads();

    for (int t = 0; t < Tn; ++t) {
        // ================= encoder LSTM gates: [256] -> [512] =================
        if (tid < Wn) {
            s->xs[tid] = input[((size_t)b * Tn + t) * Wn + tid];
            s->xs[Wn + tid] = s->h_enc[tid];
        }
        __syncthreads();
        {
            const int u = tid & 127, kc = tid >> 7;       // u: 4 rows, kc: 64 k's
            const float4* wp = ((const float4*)g_encT) + u;
            const float* xsrc = s->xs;
            float4 a0 = make_float4(0, 0, 0, 0), a1 = a0, a2 = a0, a3 = a0;
            const int k0 = kc * 64;
#pragma unroll 4
            for (int kk = 0; kk < 64; kk += 4) GEMV_BLOCK(wp, 128, k0 + kk);
            float4 acc = make_float4(a0.x + a1.x + a2.x + a3.x, a0.y + a1.y + a2.y + a3.y,
                                     a0.z + a1.z + a2.z + a3.z, a0.w + a1.w + a2.w + a3.w);
            ((float4*)s->gp)[kc * 128 + u] = acc;
        }
        __syncthreads();
        if (tid < Wn) {
            float gi = s->gp[tid]       + s->gp[512 + tid]  + s->gp[1024 + tid] + s->gp[1536 + tid] + g_benc[tid];
            float gf = s->gp[128 + tid] + s->gp[640 + tid]  + s->gp[1152 + tid] + s->gp[1664 + tid] + g_benc[128 + tid];
            float gg = s->gp[256 + tid] + s->gp[768 + tid]  + s->gp[1280 + tid] + s->gp[1792 + tid] + g_benc[256 + tid];
            float go = s->gp[384 + tid] + s->gp[896 + tid]  + s->gp[1408 + tid] + s->gp[1920 + tid] + g_benc[384 + tid];
            gi = sigm(gi); gf = sigm(gf); gg = tanhf(gg); go = sigm(go);
            float c = gf * s->c_enc[tid] + gi * gg;
            s->c_enc[tid] = c;
            s->h_enc[tid] = go * tanhf(c);
        }
        __syncthreads();

        // ================= controller LSTM gates: [768] -> [512] =================
        if (tid < Wn) {
            s->xs[tid * 5 + 0] = s->h_enc[tid];
            s->xs[tid * 5 + 1] = s->rv[tid][0];
            s->xs[tid * 5 + 2] = s->rv[tid][1];
            s->xs[tid * 5 + 3] = s->rv[tid][2];
            s->xs[tid * 5 + 4] = s->rv[tid][3];
            s->xs[640 + tid] = s->h_ctl[tid];
        }
        __syncthreads();
        {
            const int u = tid & 127, kc = tid >> 7;       // kc: 192 k's
            const float4* wp = ((const float4*)g_ctlT) + u;
            const float* xsrc = s->xs;
            float4 a0 = make_float4(0, 0, 0, 0), a1 = a0, a2 = a0, a3 = a0;
            const int k0 = kc * 192;
#pragma unroll 4
            for (int kk = 0; kk < 192; kk += 4) GEMV_BLOCK(wp, 128, k0 + kk);
            float4 acc = make_float4(a0.x + a1.x + a2.x + a3.x, a0.y + a1.y + a2.y + a3.y,
                                     a0.z + a1.z + a2.z + a3.z, a0.w + a1.w + a2.w + a3.w);
            ((float4*)s->gp)[kc * 128 + u] = acc;
        }
        __syncthreads();
        if (tid < Wn) {
            float gi = s->gp[tid]       + s->gp[512 + tid]  + s->gp[1024 + tid] + s->gp[1536 + tid] + g_bctl[tid];
            float gf = s->gp[128 + tid] + s->gp[640 + tid]  + s->gp[1152 + tid] + s->gp[1664 + tid] + g_bctl[128 + tid];
            float gg = s->gp[256 + tid] + s->gp[768 + tid]  + s->gp[1280 + tid] + s->gp[1792 + tid] + g_bctl[256 + tid];
            float go = s->gp[384 + tid] + s->gp[896 + tid]  + s->gp[1408 + tid] + s->gp[1920 + tid] + g_bctl[384 + tid];
            gi = sigm(gi); gf = sigm(gf); gg = tanhf(gg); go = sigm(go);
            float c = gf * s->c_ctl[tid] + gi * gg;
            s->c_ctl[tid] = c;
            s->h_ctl[tid] = go * tanhf(c);
        }
        __syncthreads();

        // ================= interface projection: [128] -> [919] =================
        {
            const int u = tid & 255, kc = tid >> 8;       // kc in {0,1}: 64 k's
            if (u < 230) {
                const float4* wp = ((const float4*)g_ifcT) + u;
                const float* xsrc = s->h_ctl;
                float4 a0 = make_float4(0, 0, 0, 0), a1 = a0, a2 = a0, a3 = a0;
                const int k0 = kc * 64;
#pragma unroll 4
                for (int kk = 0; kk < 64; kk += 4) GEMV_BLOCK(wp, 230, k0 + kk);
                float4 acc = make_float4(a0.x + a1.x + a2.x + a3.x, a0.y + a1.y + a2.y + a3.y,
                                         a0.z + a1.z + a2.z + a3.z, a0.w + a1.w + a2.w + a3.w);
                ((float4*)s->gp)[kc * 230 + u] = acc;
            }
        }
        __syncthreads();
        for (int j = tid; j < IFACEn; j += NTH)
            s->xi[j] = s->gp[j] + s->gp[920 + j] + g_bifc[j];
        __syncthreads();

        // ================= parse interface =================
        {
            for (int i = tid; i < Rn * Wn; i += NTH) ((float*)s->rk)[i] = tanhf(s->xi[i]);
            if (tid < Wn) {
                s->wk[tid] = tanhf(s->xi[516 + tid]);
                s->er[tid] = sigm(s->xi[645 + tid]);
                s->wv[tid] = tanhf(s->xi[773 + tid]);
            }
            if (tid >= 256 && tid < 256 + Rn) {
                int r = tid - 256;
                s->rstr[r] = softplusf(s->xi[512 + r]);
                s->fg[r] = sigm(s->xi[901 + r]);
                float a = s->xi[907 + r * 3], b2 = s->xi[908 + r * 3], c2 = s->xi[909 + r * 3];
                float m = fmaxf(a, fmaxf(b2, c2));
                float ea = expf(a - m), eb = expf(b2 - m), ec = expf(c2 - m);
                float inv = 1.f / (ea + eb + ec);
                s->rm[r][0] = ea * inv; s->rm[r][1] = eb * inv; s->rm[r][2] = ec * inv;
            }
            if (tid == NTH - 1) {
                s->scal[0] = softplusf(s->xi[644]);  // write_str
                s->scal[1] = sigm(s->xi[905]);       // alloc_gate
                s->scal[2] = sigm(s->xi[906]);       // write_gate
            }
        }
        __syncthreads();

        // ======== usage update (prev ww, prev rw) + wk norm + old-mem norms & wk dots ========
        if (tid < Nn) {
            float us = s->usage[tid];
            us = us + (1.f - us) * s->ww[tid];
            float ret = 1.f;
#pragma unroll
            for (int r = 0; r < Rn; ++r) ret *= (1.f - s->fg[r] * s->rw[r][tid]);
            s->usage[tid] = us * ret;
        }
        {
            float4 k4 = ((const float4*)s->wk)[lane];
            if (wid == 0) {
                float nv = wsum(dot4(k4, k4));
                if (lane == 0) s->scal[3] = sqrtf(nv);
            }
            for (int rr = 0; rr < 8; ++rr) {
                int n = wid * 8 + rr;
                float4 m4 = ((const float4*)s->mem[n])[lane];
                float dn = dot4(m4, m4);
                float dk = dot4(m4, k4);
                dn = wsum(dn); dk = wsum(dk);
                if (lane == 0) { s->nrm[n] = sqrtf(dn); s->wc[n] = dk; }
            }
        }
        __syncthreads();

        // ======== write content softmax over N ========
        {
            float v = -1e30f;
            if (tid < Nn) {
                v = s->wc[tid] / ((s->nrm[tid] + DELTAf) * (s->scal[3] + DELTAf)) * s->scal[0];
                s->wc[tid] = v;
            }
            float m = wmax(v);
            if (lane == 0) s->red[wid] = m;
            __syncthreads();
            if (tid == 0)
                s->scal[4] = fmaxf(fmaxf(s->red[0], s->red[1]), fmaxf(s->red[2], s->red[3]));
            __syncthreads();
            float e = 0.f;
            if (tid < Nn) { e = expf(s->wc[tid] - s->scal[4]); s->wc[tid] = e; }
            float sm = wsum(e);
            if (lane == 0) s->red[wid] = sm;
            __syncthreads();
            if (tid == 0) s->scal[5] = 1.f / (s->red[0] + s->red[1] + s->red[2] + s->red[3]);
            __syncthreads();
            if (tid < Nn) s->wc[tid] *= s->scal[5];
        }

        // ======== allocation weighting (stable rank + cumprod scan) ========
        if (tid < Nn) s->uu[tid] = DELTAf + (1.f - DELTAf) * s->usage[tid];
        __syncthreads();
        if (tid < Nn) {
            float un = s->uu[tid];
            int rk_ = 0;
#pragma unroll 4
            for (int j = 0; j < Nn; ++j) {
                float uj = s->uu[j];
                rk_ += (uj < un) || (uj == un && j < tid);
            }
            s->rnk[tid] = rk_;
            s->psu[rk_] = un;   // scatter into sorted order (ranks are a permutation)
        }
        __syncthreads();
        for (int off = 1; off < Nn; off <<= 1) {   // inclusive cumprod (Hillis-Steele)
            float v = 0.f;
            if (tid < Nn) { v = s->psu[tid]; if (tid >= off) v *= s->psu[tid - off]; }
            __syncthreads();
            if (tid < Nn) s->psu[tid] = v;
            __syncthreads();
        }
        if (tid < Nn) {
            int r_ = s->rnk[tid];
            float excl = (r_ == 0) ? 1.f : s->psu[r_ - 1];
            s->alloc_[tid] = (1.f - s->uu[tid]) * excl;
        }
        __syncthreads();

        // ======== new write weighting + its sum ========
        {
            float v = 0.f;
            if (tid < Nn) {
                float ag = s->scal[1], wg = s->scal[2];
                v = wg * (ag * s->alloc_[tid] + (1.f - ag) * s->wc[tid]);
                s->ww[tid] = v;
            }
            float sm = wsum(v);
            if (lane == 0) s->red[wid] = sm;
            __syncthreads();
            if (tid == 0) s->scal[6] = s->red[0] + s->red[1] + s->red[2] + s->red[3];
            __syncthreads();
        }

        // ======== memory erase+write, link update (old prec) ========
        {
            float4* m4 = (float4*)s->mem;
            const float4* e4p = (const float4*)s->er;
            const float4* v4p = (const float4*)s->wv;
#pragma unroll
            for (int it = 0; it < 8; ++it) {
                int idx = tid + it * NTH;
                int n = idx >> 5, q = idx & 31;
                float wwn = s->ww[n];
                float4 m = m4[idx], e = e4p[q], v = v4p[q];
                m.x = m.x * (1.f - wwn * e.x) + wwn * v.x;
                m.y = m.y * (1.f - wwn * e.y) + wwn * v.y;
                m.z = m.z * (1.f - wwn * e.z) + wwn * v.z;
                m.w = m.w * (1.f - wwn * e.w) + wwn * v.w;
                m4[idx] = m;
            }
            float4* l4 = (float4*)s->lnk;
            const float4* wwp = (const float4*)s->ww;
            const float4* pcp = (const float4*)s->prec;
#pragma unroll
            for (int it = 0; it < 8; ++it) {
                int idx = tid + it * NTH;
                int i = idx >> 5, q = idx & 31;
                float wwi = s->ww[i];
                float4 L = l4[idx], wj = wwp[q], pj = pcp[q];
                L.x = (1.f - wwi - wj.x) * L.x + wwi * pj.x;
                L.y = (1.f - wwi - wj.y) * L.y + wwi * pj.y;
                L.z = (1.f - wwi - wj.z) * L.z + wwi * pj.z;
                L.w = (1.f - wwi - wj.w) * L.w + wwi * pj.w;
                if ((i >> 2) == q) ((float*)&L)[i & 3] = 0.f;   // zero diagonal
                l4[idx] = L;
            }
        }
        __syncthreads();

        // ======== precedence update + new-mem norms & read-key dots ========
        if (tid < Nn) s->prec[tid] = (1.f - s->scal[6]) * s->prec[tid] + s->ww[tid];
        {
            if (wid < Rn) {
                float4 k4 = ((const float4*)s->rk[wid])[lane];
                float nv = wsum(dot4(k4, k4));
                if (lane == 0) s->rknorm[wid] = sqrtf(nv);
            }
            float4 k0 = ((const float4*)s->rk[0])[lane];
            float4 k1 = ((const float4*)s->rk[1])[lane];
            float4 k2 = ((const float4*)s->rk[2])[lane];
            float4 k3 = ((const float4*)s->rk[3])[lane];
            for (int rr = 0; rr < 8; ++rr) {
                int n = wid * 8 + rr;
                float4 m = ((const float4*)s->mem[n])[lane];
                float dn = dot4(m, m);
                float d0 = dot4(m, k0);
                float d1 = dot4(m, k1);
                float d2 = dot4(m, k2);
                float d3 = dot4(m, k3);
                dn = wsum(dn); d0 = wsum(d0); d1 = wsum(d1); d2 = wsum(d2); d3 = wsum(d3);
                if (lane == 0) {
                    s->nrm[n] = sqrtf(dn);
                    s->rc[0][n] = d0; s->rc[1][n] = d1; s->rc[2][n] = d2; s->rc[3][n] = d3;
                }
            }
        }
        __syncthreads();

        // ======== read content softmax (4 segments of 128) ========
        {
            int r_ = tid >> 7, n = tid & 127;
            float v = s->rc[r_][n] / ((s->nrm[n] + DELTAf) * (s->rknorm[r_] + DELTAf)) * s->rstr[r_];
            float m = wmax(v);
            if (lane == 0) s->red[wid] = m;
            __syncthreads();
            if (tid < Rn)
                s->segred[tid] = fmaxf(fmaxf(s->red[4 * tid], s->red[4 * tid + 1]),
                                       fmaxf(s->red[4 * tid + 2], s->red[4 * tid + 3]));
            __syncthreads();
            float e = expf(v - s->segred[r_]);
            float sm = wsum(e);
            if (lane == 0) s->red[wid] = sm;
            __syncthreads();
            if (tid < Rn)
                s->segred[tid] = 1.f / (s->red[4 * tid] + s->red[4 * tid + 1] +
                                        s->red[4 * tid + 2] + s->red[4 * tid + 3]);
            __syncthreads();
            s->rc[r_][n] = e * s->segred[r_];
        }
        __syncthreads();

        // ======== forward / backward temporal weights (new link, OLD rw) ========
        {
            // fw[r][i] = sum_j link[i][j] * rw[r][j]
            for (int rr = 0; rr < 32; ++rr) {
                int o = wid * 32 + rr;
                int r_ = o >> 7, i = o & 127;
                float4 L = ((const float4*)s->lnk[i])[lane];
                float4 w4 = ((const float4*)s->rw[r_])[lane];
                float acc = wsum(dot4(L, w4));
                if (lane == 0) s->fwv[r_][i] = acc;
            }
            // bw[r][i] = sum_j rw[r][j] * link[j][i]
            int r_ = tid >> 7, i = tid & 127;
            float acc = 0.f;
#pragma unroll 4
            for (int j = 0; j < Nn; ++j)
                acc += s->rw[r_][j] * s->lnk[j][i];
            s->bwv[r_][i] = acc;
        }
        __syncthreads();

        // ======== combine read modes ========
        {
            int r_ = tid >> 7, n = tid & 127;
            s->rwn[r_][n] = s->rm[r_][0] * s->bwv[r_][n]
                          + s->rm[r_][1] * s->fwv[r_][n]
                          + s->rm[r_][2] * s->rc[r_][n];
        }
        __syncthreads();

        // ======== read vectors rv[w][r] = sum_n rwn[r][n]*mem[n][w]; commit rw ========
        {
            int r_ = tid >> 7, w = tid & 127;
            float acc = 0.f;
#pragma unroll 4
            for (int n = 0; n < Nn; ++n)
                acc += s->rwn[r_][n] * s->mem[n][w];
            s->rv[w][r_] = acc;
            ((float*)s->rw)[tid] = ((float*)s->rwn)[tid];
        }
        __syncthreads();

        // ================= output projection: [640] -> [128] =================
        if (tid < Wn) s->xs[tid] = s->h_ctl[tid];
        s->xs[Wn + tid] = ((float*)s->rv)[tid];   // rv flat is w*4+r, matches reshape
        __syncthreads();
        {
            const int u = tid & 31, kc = tid >> 5;    // u: 4 out rows, kc: 40 k's
            const float4* wp = ((const float4*)g_outT) + u;
            const float* xsrc = s->xs;
            float4 a0 = make_float4(0, 0, 0, 0), a1 = a0, a2 = a0, a3 = a0;
            const int k0 = kc * 40;
#pragma unroll 5
            for (int kk = 0; kk < 40; kk += 4) GEMV_BLOCK(wp, 32, k0 + kk);
            float4 acc = make_float4(a0.x + a1.x + a2.x + a3.x, a0.y + a1.y + a2.y + a3.y,
                                     a0.z + a1.z + a2.z + a3.z, a0.w + a1.w + a2.w + a3.w);
            ((float4*)s->gp)[kc * 32 + u] = acc;
        }
        __syncthreads();
        if (tid < Wn) {
            float acc = g_bout[tid];
#pragma unroll
            for (int kc = 0; kc < 16; ++kc) acc += s->gp[kc * 128 + tid];
            out[((size_t)b * Tn + t) * Wn + tid] = acc;
        }
        __syncthreads();
    }
}

extern "C" void kernel_launch(void* const* d_in, const int* in_sizes, int n_in,
                              void* d_out, int out_size) {
    const float* input   = (const float*)d_in[0];
    // d_in[1] = source_lengths (all == T, unused)
    const float* enc_Wih = (const float*)d_in[2];
    const float* enc_Whh = (const float*)d_in[3];
    const float* enc_bih = (const float*)d_in[4];
    const float* enc_bhh = (const float*)d_in[5];
    const float* ctl_Wih = (const float*)d_in[6];
    const float* ctl_Whh = (const float*)d_in[7];
    const float* ctl_bih = (const float*)d_in[8];
    const float* ctl_bhh = (const float*)d_in[9];
    const float* iface_W = (const float*)d_in[10];
    const float* iface_b = (const float*)d_in[11];
    const float* out_W   = (const float*)d_in[12];
    const float* out_b   = (const float*)d_in[13];
    float* out = (float*)d_out;

    prep_kernel<<<448, 256>>>(enc_Wih, enc_Whh, enc_bih, enc_bhh,
                              ctl_Wih, ctl_Whh, ctl_bih, ctl_bhh,
                              iface_W, iface_b, out_W, out_b);

    int smem = (int)sizeof(Smem);
    cudaFuncSetAttribute(dnc_kernel, cudaFuncAttributeMaxDynamicSharedMemorySize, smem);
    dnc_kernel<<<Bn, NTH, smem>>>(input, out);
}

// round 4
// speedup vs baseline: 2.6901x; 1.1036x over previous
#include <cuda_runtime.h>
#include <cstddef>
#include <cstdint>

#define Bn 32
#define Tn 256
#define Wn 128
#define Rn 4
#define Nn 128
#define IFACEn 919
#define NTH 1024
#define NWARP 32
#define DELTAf 1e-6f

// -------- transposed-weight scratch (written once per launch by prep kernel) --------
__device__ float g_encT[256 * 512];   // [k][j]
__device__ float g_ctlT[768 * 512];   // [k][j]  k = xc(640)||h(128)
__device__ float g_ifcT[128 * 920];   // [k][j]  j padded 919->920
__device__ float g_outT[640 * 128];   // [k][o]
__device__ float g_benc[512];
__device__ float g_bctl[512];
__device__ float g_bifc[920];
__device__ float g_bout[128];

__global__ void prep_kernel(
    const float* __restrict__ enc_Wih, const float* __restrict__ enc_Whh,
    const float* __restrict__ enc_bih, const float* __restrict__ enc_bhh,
    const float* __restrict__ ctl_Wih, const float* __restrict__ ctl_Whh,
    const float* __restrict__ ctl_bih, const float* __restrict__ ctl_bhh,
    const float* __restrict__ iface_W, const float* __restrict__ iface_b,
    const float* __restrict__ out_W, const float* __restrict__ out_b)
{
    const int idx = blockIdx.x * blockDim.x + threadIdx.x;
    const int stride = gridDim.x * blockDim.x;
    for (int i = idx; i < 256 * 512; i += stride) {
        int k = i >> 9, j = i & 511;
        g_encT[i] = (k < 128) ? enc_Wih[(size_t)j * 128 + k]
                              : enc_Whh[(size_t)j * 128 + (k - 128)];
    }
    for (int i = idx; i < 768 * 512; i += stride) {
        int k = i >> 9, j = i & 511;
        g_ctlT[i] = (k < 640) ? ctl_Wih[(size_t)j * 640 + k]
                              : ctl_Whh[(size_t)j * 128 + (k - 640)];
    }
    for (int i = idx; i < 128 * 920; i += stride) {
        int k = i / 920, j = i - k * 920;
        g_ifcT[i] = (j < IFACEn) ? iface_W[(size_t)j * 128 + k] : 0.f;
    }
    for (int i = idx; i < 640 * 128; i += stride) {
        int k = i >> 7, o = i & 127;
        g_outT[i] = out_W[(size_t)o * 640 + k];
    }
    if (idx < 512) {
        g_benc[idx] = enc_bih[idx] + enc_bhh[idx];
        g_bctl[idx] = ctl_bih[idx] + ctl_bhh[idx];
    }
    if (idx < 920) g_bifc[idx] = (idx < IFACEn) ? iface_b[idx] : 0.f;
    if (idx < 128) g_bout[idx] = out_b[idx];
}

struct Smem {
    float mem[Nn][Wn];     // 64KB
    float lnk[Nn][Nn];     // 64KB
    float gp[4096];        // GEMV partial sums (16KB)
    float xs[768];
    float bufo[920];       // local GEMV partial (this CTA's half-k sum)
    float pe[512];         // peer partials, per GEMV (distinct buffers!)
    float pc[512];
    float pi[920];
    float po[128];
    float h_enc[Wn], c_enc[Wn];
    float h_ctl[Wn], c_ctl[Wn];
    float rv[Wn][Rn];      // read vectors [w][r]  (flat = w*4+r)
    float rw[Rn][Nn];
    float rwn[Rn][Nn];
    float ww[Nn];
    float prec[Nn];
    float usage[Nn];
    float xi[920];
    float rk[Rn][Wn];
    float wk[Wn];
    float er[Wn];
    float wv[Wn];
    float rstr[Rn];
    float fg[Rn];
    float rknorm[Rn];
    float rm[Rn][3];
    float wc[Nn];
    float uu[Nn];
    float psu[Nn];
    float alloc_[Nn];
    float nrm[Nn];
    float rc[Rn][Nn];
    float fwv[Rn][Nn];
    float bwv[Rn][Nn];
    float red[NWARP];
    float segred[Rn];
    float scal[8];
    int   rnk[Nn];
};

__device__ __forceinline__ float sigm(float x) { return 1.0f / (1.0f + expf(-x)); }
__device__ __forceinline__ float softplusf(float x) {
    return (x > 0.f) ? (x + log1pf(expf(-x))) : log1pf(expf(x));
}
__device__ __forceinline__ float wsum(float v) {
    v += __shfl_xor_sync(0xffffffffu, v, 16);
    v += __shfl_xor_sync(0xffffffffu, v, 8);
    v += __shfl_xor_sync(0xffffffffu, v, 4);
    v += __shfl_xor_sync(0xffffffffu, v, 2);
    v += __shfl_xor_sync(0xffffffffu, v, 1);
    return v;
}
__device__ __forceinline__ float wmax(float v) {
    v = fmaxf(v, __shfl_xor_sync(0xffffffffu, v, 16));
    v = fmaxf(v, __shfl_xor_sync(0xffffffffu, v, 8));
    v = fmaxf(v, __shfl_xor_sync(0xffffffffu, v, 4));
    v = fmaxf(v, __shfl_xor_sync(0xffffffffu, v, 2));
    v = fmaxf(v, __shfl_xor_sync(0xffffffffu, v, 1));
    return v;
}
__device__ __forceinline__ float dot4(float4 a, float4 b) {
    return a.x * b.x + a.y * b.y + a.z * b.z + a.w * b.w;
}
__device__ __forceinline__ void dsmem_store(void* local_ptr, uint32_t peer, float v) {
    uint32_t la = (uint32_t)__cvta_generic_to_shared(local_ptr);
    uint32_t rem;
    asm volatile("mapa.shared::cluster.u32 %0, %1, %2;" : "=r"(rem) : "r"(la), "r"(peer));
    asm volatile("st.shared::cluster.f32 [%0], %1;" :: "r"(rem), "f"(v) : "memory");
}
#define CLUSTER_SYNC() do { \
    asm volatile("barrier.cluster.arrive.aligned;" ::: "memory"); \
    asm volatile("barrier.cluster.wait.aligned;" ::: "memory"); } while (0)

// 4 k's per block, 4 weight loads, 2 float4 accumulators (register economy)
#define GEMV_BLK(WP, RS, K)                                                    \
    {                                                                          \
        float4 xv = *(const float4*)&xsrc[(K)];                                \
        float4 w0 = (WP)[(size_t)((K) + 0) * (RS)];                            \
        float4 w1 = (WP)[(size_t)((K) + 1) * (RS)];                            \
        float4 w2 = (WP)[(size_t)((K) + 2) * (RS)];                            \
        float4 w3 = (WP)[(size_t)((K) + 3) * (RS)];                            \
        a0.x += xv.x * w0.x; a0.y += xv.x * w0.y; a0.z += xv.x * w0.z; a0.w += xv.x * w0.w; \
        a1.x += xv.y * w1.x; a1.y += xv.y * w1.y; a1.z += xv.y * w1.z; a1.w += xv.y * w1.w; \
        a0.x += xv.z * w2.x; a0.y += xv.z * w2.y; a0.z += xv.z * w2.z; a0.w += xv.z * w2.w; \
        a1.x += xv.w * w3.x; a1.y += xv.w * w3.y; a1.z += xv.w * w3.z; a1.w += xv.w * w3.w; \
    }

__global__ void __launch_bounds__(NTH, 1) __cluster_dims__(2, 1, 1) dnc_kernel(
    const float* __restrict__ input,
    float* __restrict__ out)
{
    extern __shared__ char smraw[];
    Smem* s = reinterpret_cast<Smem*>(smraw);
    const int b = blockIdx.x >> 1;
    const uint32_t rank = blockIdx.x & 1;
    const uint32_t peer = rank ^ 1;
    const int tid = threadIdx.x;
    const int wid = tid >> 5;
    const int lane = tid & 31;

    // ---- zero all recurrent state ----
    {
        float* p = &s->mem[0][0];   // mem + lnk contiguous
        for (int i = tid; i < Nn * Wn + Nn * Nn; i += NTH) p[i] = 0.f;
        if (tid < Wn) {
            s->h_enc[tid] = 0.f; s->c_enc[tid] = 0.f;
            s->h_ctl[tid] = 0.f; s->c_ctl[tid] = 0.f;
            s->ww[tid] = 0.f; s->prec[tid] = 0.f; s->usage[tid] = 0.f;
        }
        if (tid < 512) { ((float*)s->rw)[tid] = 0.f; ((float*)s->rv)[tid] = 0.f; }
    }
    __syncthreads();

    for (int t = 0; t < Tn; ++t) {
        // ===== E1: encoder input =====
        if (tid < Wn) {
            s->xs[tid] = input[((size_t)b * Tn + t) * Wn + tid];
            s->xs[Wn + tid] = s->h_enc[tid];
        }
        __syncthreads();
        // ===== E2: enc GEMV partial (this CTA's half of k) =====
        {
            const int u = tid & 127, kc = tid >> 7;        // 128 j-groups, 8 k-chunks
            const float4* wp = ((const float4*)g_encT) + u;
            const float* xsrc = s->xs;
            float4 a0 = make_float4(0, 0, 0, 0), a1 = a0;
            const int k0 = (int)rank * 128 + kc * 16;
#pragma unroll 2
            for (int kk = 0; kk < 16; kk += 4) GEMV_BLK(wp, 128, k0 + kk);
            ((float4*)s->gp)[kc * 128 + u] =
                make_float4(a0.x + a1.x, a0.y + a1.y, a0.z + a1.z, a0.w + a1.w);
        }
        __syncthreads();
        // ===== E3: reduce + exchange =====
        if (tid < 512) {
            float p = 0.f;
#pragma unroll
            for (int kc = 0; kc < 8; ++kc) p += s->gp[kc * 512 + tid];
            s->bufo[tid] = p;
            dsmem_store(&s->pe[tid], peer, p);
        }
        CLUSTER_SYNC();
        // ===== E4: enc cell =====
        if (tid < Wn) {
            float gi = s->bufo[tid]       + s->pe[tid]       + g_benc[tid];
            float gf = s->bufo[128 + tid] + s->pe[128 + tid] + g_benc[128 + tid];
            float gg = s->bufo[256 + tid] + s->pe[256 + tid] + g_benc[256 + tid];
            float go = s->bufo[384 + tid] + s->pe[384 + tid] + g_benc[384 + tid];
            gi = sigm(gi); gf = sigm(gf); gg = tanhf(gg); go = sigm(go);
            float c = gf * s->c_enc[tid] + gi * gg;
            s->c_enc[tid] = c;
            s->h_enc[tid] = go * tanhf(c);
        }
        __syncthreads();

        // ===== C1: controller input (interleaved cat) =====
        if (tid < Wn) {
            s->xs[tid * 5 + 0] = s->h_enc[tid];
            s->xs[tid * 5 + 1] = s->rv[tid][0];
            s->xs[tid * 5 + 2] = s->rv[tid][1];
            s->xs[tid * 5 + 3] = s->rv[tid][2];
            s->xs[tid * 5 + 4] = s->rv[tid][3];
            s->xs[640 + tid] = s->h_ctl[tid];
        }
        __syncthreads();
        // ===== C2: ctl GEMV partial =====
        {
            const int u = tid & 127, kc = tid >> 7;        // 8 chunks x 48 k
            const float4* wp = ((const float4*)g_ctlT) + u;
            const float* xsrc = s->xs;
            float4 a0 = make_float4(0, 0, 0, 0), a1 = a0;
            const int k0 = (int)rank * 384 + kc * 48;
#pragma unroll 2
            for (int kk = 0; kk < 48; kk += 4) GEMV_BLK(wp, 128, k0 + kk);
            ((float4*)s->gp)[kc * 128 + u] =
                make_float4(a0.x + a1.x, a0.y + a1.y, a0.z + a1.z, a0.w + a1.w);
        }
        __syncthreads();
        // ===== C3: reduce + exchange =====
        if (tid < 512) {
            float p = 0.f;
#pragma unroll
            for (int kc = 0; kc < 8; ++kc) p += s->gp[kc * 512 + tid];
            s->bufo[tid] = p;
            dsmem_store(&s->pc[tid], peer, p);
        }
        CLUSTER_SYNC();
        // ===== C4: ctl cell =====
        if (tid < Wn) {
            float gi = s->bufo[tid]       + s->pc[tid]       + g_bctl[tid];
            float gf = s->bufo[128 + tid] + s->pc[128 + tid] + g_bctl[128 + tid];
            float gg = s->bufo[256 + tid] + s->pc[256 + tid] + g_bctl[256 + tid];
            float go = s->bufo[384 + tid] + s->pc[384 + tid] + g_bctl[384 + tid];
            gi = sigm(gi); gf = sigm(gf); gg = tanhf(gg); go = sigm(go);
            float c = gf * s->c_ctl[tid] + gi * gg;
            s->c_ctl[tid] = c;
            s->h_ctl[tid] = go * tanhf(c);
        }
        __syncthreads();

        // ===== I1: iface GEMV partial (x = h_ctl) =====
        if (tid < 920) {
            const int kc = tid / 230, u = tid - kc * 230;  // 4 chunks x 16 k, 230 j-groups
            const float4* wp = ((const float4*)g_ifcT) + u;
            const float* xsrc = s->h_ctl;
            float4 a0 = make_float4(0, 0, 0, 0), a1 = a0;
            const int k0 = (int)rank * 64 + kc * 16;
#pragma unroll 2
            for (int kk = 0; kk < 16; kk += 4) GEMV_BLK(wp, 230, k0 + kk);
            ((float4*)(s->gp + kc * 920))[u] =
                make_float4(a0.x + a1.x, a0.y + a1.y, a0.z + a1.z, a0.w + a1.w);
        }
        __syncthreads();
        // ===== I2: reduce + exchange =====
        if (tid < 920) {
            float p = s->gp[tid] + s->gp[920 + tid] + s->gp[1840 + tid] + s->gp[2760 + tid];
            s->bufo[tid] = p;
            dsmem_store(&s->pi[tid], peer, p);
        }
        CLUSTER_SYNC();
        if (tid < IFACEn) s->xi[tid] = s->bufo[tid] + s->pi[tid] + g_bifc[tid];
        __syncthreads();

        // ===== parse interface =====
        {
            if (tid < 512) ((float*)s->rk)[tid] = tanhf(s->xi[tid]);
            if (tid >= 512 && tid < 640) {
                int i = tid - 512;
                s->wk[i] = tanhf(s->xi[516 + i]);
                s->er[i] = sigm(s->xi[645 + i]);
                s->wv[i] = tanhf(s->xi[773 + i]);
            }
            if (tid >= 640 && tid < 640 + Rn) {
                int r = tid - 640;
                s->rstr[r] = softplusf(s->xi[512 + r]);
                s->fg[r] = sigm(s->xi[901 + r]);
                float a = s->xi[907 + r * 3], b2 = s->xi[908 + r * 3], c2 = s->xi[909 + r * 3];
                float m = fmaxf(a, fmaxf(b2, c2));
                float ea = expf(a - m), eb = expf(b2 - m), ec = expf(c2 - m);
                float inv = 1.f / (ea + eb + ec);
                s->rm[r][0] = ea * inv; s->rm[r][1] = eb * inv; s->rm[r][2] = ec * inv;
            }
            if (tid == NTH - 1) {
                s->scal[0] = softplusf(s->xi[644]);  // write_str
                s->scal[1] = sigm(s->xi[905]);       // alloc_gate
                s->scal[2] = sigm(s->xi[906]);       // write_gate
            }
        }
        __syncthreads();

        // ===== usage update + wk norm + old-mem norms & wk dots =====
        if (tid < Nn) {
            float us = s->usage[tid];
            us = us + (1.f - us) * s->ww[tid];
            float ret = 1.f;
#pragma unroll
            for (int r = 0; r < Rn; ++r) ret *= (1.f - s->fg[r] * s->rw[r][tid]);
            s->usage[tid] = us * ret;
        }
        {
            float4 k4 = ((const float4*)s->wk)[lane];
            if (wid == 0) {
                float nv = wsum(dot4(k4, k4));
                if (lane == 0) s->scal[3] = sqrtf(nv);
            }
#pragma unroll
            for (int rr = 0; rr < 4; ++rr) {
                int n = wid * 4 + rr;
                float4 m4 = ((const float4*)s->mem[n])[lane];
                float dn = dot4(m4, m4);
                float dk = dot4(m4, k4);
                dn = wsum(dn); dk = wsum(dk);
                if (lane == 0) { s->nrm[n] = sqrtf(dn); s->wc[n] = dk; }
            }
        }
        __syncthreads();

        // ===== write content softmax over N =====
        {
            float v = -1e30f;
            if (tid < Nn) {
                v = s->wc[tid] / ((s->nrm[tid] + DELTAf) * (s->scal[3] + DELTAf)) * s->scal[0];
                s->wc[tid] = v;
            }
            float m = wmax(v);
            if (lane == 0) s->red[wid] = m;
            __syncthreads();
            if (tid < 32) {
                float mm = wmax(s->red[tid]);
                if (tid == 0) s->scal[4] = mm;
            }
            __syncthreads();
            float e = 0.f;
            if (tid < Nn) { e = expf(s->wc[tid] - s->scal[4]); s->wc[tid] = e; }
            float sm = wsum(e);
            if (lane == 0) s->red[wid] = sm;
            __syncthreads();
            if (tid < 32) {
                float ss = wsum(s->red[tid]);
                if (tid == 0) s->scal[5] = 1.f / ss;
            }
            __syncthreads();
            if (tid < Nn) s->wc[tid] *= s->scal[5];
        }

        // ===== allocation weighting (stable rank + single-warp cumprod scan) =====
        if (tid < Nn) s->uu[tid] = DELTAf + (1.f - DELTAf) * s->usage[tid];
        __syncthreads();
        if (tid < Nn) {
            float un = s->uu[tid];
            int rk_ = 0;
#pragma unroll 8
            for (int j = 0; j < Nn; ++j) {
                float uj = s->uu[j];
                rk_ += (uj < un) || (uj == un && j < tid);
            }
            s->rnk[tid] = rk_;
            s->psu[rk_] = un;   // scatter into sorted order (ranks are a permutation)
        }
        __syncthreads();
        if (wid == 0) {        // inclusive cumprod of psu[0..127], one warp
            float v0 = s->psu[lane * 4], v1 = s->psu[lane * 4 + 1];
            float v2 = s->psu[lane * 4 + 2], v3 = s->psu[lane * 4 + 3];
            float l1 = v0 * v1, l2 = l1 * v2, l3 = l2 * v3;
            float run = l3;
#pragma unroll
            for (int off = 1; off < 32; off <<= 1) {
                float up = __shfl_up_sync(0xffffffffu, run, off);
                if (lane >= off) run *= up;
            }
            float ex = __shfl_up_sync(0xffffffffu, run, 1);
            if (lane == 0) ex = 1.f;
            s->psu[lane * 4]     = ex * v0;
            s->psu[lane * 4 + 1] = ex * l1;
            s->psu[lane * 4 + 2] = ex * l2;
            s->psu[lane * 4 + 3] = ex * l3;
        }
        __syncthreads();
        if (tid < Nn) {
            int r_ = s->rnk[tid];
            float excl = (r_ == 0) ? 1.f : s->psu[r_ - 1];
            s->alloc_[tid] = (1.f - s->uu[tid]) * excl;
        }
        __syncthreads();

        // ===== new write weighting + its sum =====
        {
            float v = 0.f;
            if (tid < Nn) {
                float ag = s->scal[1], wg = s->scal[2];
                v = wg * (ag * s->alloc_[tid] + (1.f - ag) * s->wc[tid]);
                s->ww[tid] = v;
            }
            float sm = wsum(v);
            if (lane == 0) s->red[wid] = sm;
            __syncthreads();
            if (tid < 32) {
                float ss = wsum(s->red[tid]);
                if (tid == 0) s->scal[6] = ss;
            }
            __syncthreads();
        }

        // ===== memory erase+write, link update (old prec) =====
        {
            float4* m4 = (float4*)s->mem;
            const float4* e4p = (const float4*)s->er;
            const float4* v4p = (const float4*)s->wv;
#pragma unroll
            for (int it = 0; it < 4; ++it) {
                int idx = tid + it * NTH;
                int n = idx >> 5, q = idx & 31;
                float wwn = s->ww[n];
                float4 m = m4[idx], e = e4p[q], v = v4p[q];
                m.x = m.x * (1.f - wwn * e.x) + wwn * v.x;
                m.y = m.y * (1.f - wwn * e.y) + wwn * v.y;
                m.z = m.z * (1.f - wwn * e.z) + wwn * v.z;
                m.w = m.w * (1.f - wwn * e.w) + wwn * v.w;
                m4[idx] = m;
            }
            float4* l4 = (float4*)s->lnk;
            const float4* wwp = (const float4*)s->ww;
            const float4* pcp = (const float4*)s->prec;
#pragma unroll
            for (int it = 0; it < 4; ++it) {
                int idx = tid + it * NTH;
                int i = idx >> 5, q = idx & 31;
                float wwi = s->ww[i];
                float4 L = l4[idx], wj = wwp[q], pj = pcp[q];
                L.x = (1.f - wwi - wj.x) * L.x + wwi * pj.x;
                L.y = (1.f - wwi - wj.y) * L.y + wwi * pj.y;
                L.z = (1.f - wwi - wj.z) * L.z + wwi * pj.z;
                L.w = (1.f - wwi - wj.w) * L.w + wwi * pj.w;
                if ((i >> 2) == q) ((float*)&L)[i & 3] = 0.f;   // zero diagonal
                l4[idx] = L;
            }
        }
        __syncthreads();

        // ===== precedence update + new-mem norms & read-key dots =====
        if (tid < Nn) s->prec[tid] = (1.f - s->scal[6]) * s->prec[tid] + s->ww[tid];
        {
            if (wid < Rn) {
                float4 k4 = ((const float4*)s->rk[wid])[lane];
                float nv = wsum(dot4(k4, k4));
                if (lane == 0) s->rknorm[wid] = sqrtf(nv);
            }
            float4 k0 = ((const float4*)s->rk[0])[lane];
            float4 k1 = ((const float4*)s->rk[1])[lane];
            float4 k2 = ((const float4*)s->rk[2])[lane];
            float4 k3 = ((const float4*)s->rk[3])[lane];
#pragma unroll
            for (int rr = 0; rr < 4; ++rr) {
                int n = wid * 4 + rr;
                float4 m = ((const float4*)s->mem[n])[lane];
                float dn = dot4(m, m);
                float d0 = dot4(m, k0);
                float d1 = dot4(m, k1);
                float d2 = dot4(m, k2);
                float d3 = dot4(m, k3);
                dn = wsum(dn); d0 = wsum(d0); d1 = wsum(d1); d2 = wsum(d2); d3 = wsum(d3);
                if (lane == 0) {
                    s->nrm[n] = sqrtf(dn);
                    s->rc[0][n] = d0; s->rc[1][n] = d1; s->rc[2][n] = d2; s->rc[3][n] = d3;
                }
            }
        }
        __syncthreads();

        // ===== read content softmax (4 segments of 128; warps 0-15 carry data) =====
        {
            float v = -1e30f, e = 0.f;
            int r_ = 0, n = 0;
            if (tid < 512) {
                r_ = tid >> 7; n = tid & 127;
                v = s->rc[r_][n] / ((s->nrm[n] + DELTAf) * (s->rknorm[r_] + DELTAf)) * s->rstr[r_];
            }
            float m = wmax(v);
            if (lane == 0) s->red[wid] = m;
            __syncthreads();
            if (tid < Rn)
                s->segred[tid] = fmaxf(fmaxf(s->red[4 * tid], s->red[4 * tid + 1]),
                                       fmaxf(s->red[4 * tid + 2], s->red[4 * tid + 3]));
            __syncthreads();
            if (tid < 512) e = expf(v - s->segred[r_]);
            float sm = wsum(e);
            if (lane == 0) s->red[wid] = sm;
            __syncthreads();
            if (tid < Rn)
                s->segred[tid] = 1.f / (s->red[4 * tid] + s->red[4 * tid + 1] +
                                        s->red[4 * tid + 2] + s->red[4 * tid + 3]);
            __syncthreads();
            if (tid < 512) s->rc[r_][n] = e * s->segred[r_];
        }
        __syncthreads();

        // ===== forward / backward temporal weights (new link, OLD rw) =====
        {
            // fw[r][i] = sum_j link[i][j] * rw[r][j]
#pragma unroll
            for (int rr = 0; rr < 16; ++rr) {
                int o = wid * 16 + rr;
                int r_ = o >> 7, i = o & 127;
                float4 L = ((const float4*)s->lnk[i])[lane];
                float4 w4 = ((const float4*)s->rw[r_])[lane];
                float acc = wsum(dot4(L, w4));
                if (lane == 0) s->fwv[r_][i] = acc;
            }
            // bw[r][i] = sum_j rw[r][j] * link[j][i]
            if (tid < 512) {
                int r_ = tid >> 7, i = tid & 127;
                float acc = 0.f;
#pragma unroll 4
                for (int j = 0; j < Nn; ++j)
                    acc += s->rw[r_][j] * s->lnk[j][i];
                s->bwv[r_][i] = acc;
            }
        }
        __syncthreads();

        // ===== combine read modes =====
        if (tid < 512) {
            int r_ = tid >> 7, n = tid & 127;
            s->rwn[r_][n] = s->rm[r_][0] * s->bwv[r_][n]
                          + s->rm[r_][1] * s->fwv[r_][n]
                          + s->rm[r_][2] * s->rc[r_][n];
        }
        __syncthreads();

        // ===== read vectors rv[w][r] = sum_n rwn[r][n]*mem[n][w]; commit rw =====
        if (tid < 512) {
            int r_ = tid >> 7, w = tid & 127;
            float acc = 0.f;
#pragma unroll 4
            for (int n = 0; n < Nn; ++n)
                acc += s->rwn[r_][n] * s->mem[n][w];
            s->rv[w][r_] = acc;
            ((float*)s->rw)[tid] = ((float*)s->rwn)[tid];
        }
        __syncthreads();

        // ===== O1: output-proj input =====
        if (tid < 512) {
            s->xs[128 + tid] = ((float*)s->rv)[tid];   // rv flat = w*4+r
            if (tid < 128) s->xs[tid] = s->h_ctl[tid];
        }
        __syncthreads();
        // ===== O2: out GEMV partial =====
        if (tid < 512) {
            const int u = tid & 31, kc = tid >> 5;     // 16 chunks x 20 k
            const float4* wp = ((const float4*)g_outT) + u;
            const float* xsrc = s->xs;
            float4 a0 = make_float4(0, 0, 0, 0), a1 = a0;
            const int k0 = (int)rank * 320 + kc * 20;
#pragma unroll 2
            for (int kk = 0; kk < 20; kk += 4) GEMV_BLK(wp, 32, k0 + kk);
            ((float4*)s->gp)[kc * 32 + u] =
                make_float4(a0.x + a1.x, a0.y + a1.y, a0.z + a1.z, a0.w + a1.w);
        }
        __syncthreads();
        // ===== O3: reduce + exchange =====
        if (tid < 128) {
            float p = 0.f;
#pragma unroll
            for (int kc = 0; kc < 16; ++kc) p += s->gp[kc * 128 + tid];
            s->bufo[tid] = p;
            dsmem_store(&s->po[tid], peer, p);
        }
        CLUSTER_SYNC();
        // ===== O4: write output (rank 0 only) =====
        if (rank == 0 && tid < Wn)
            out[((size_t)b * Tn + t) * Wn + tid] = s->bufo[tid] + s->po[tid] + g_bout[tid];
        __syncthreads();
    }
}

extern "C" void kernel_launch(void* const* d_in, const int* in_sizes, int n_in,
                              void* d_out, int out_size) {
    const float* input   = (const float*)d_in[0];
    // d_in[1] = source_lengths (all == T, unused)
    const float* enc_Wih = (const float*)d_in[2];
    const float* enc_Whh = (const float*)d_in[3];
    const float* enc_bih = (const float*)d_in[4];
    const float* enc_bhh = (const float*)d_in[5];
    const float* ctl_Wih = (const float*)d_in[6];
    const float* ctl_Whh = (const float*)d_in[7];
    const float* ctl_bih = (const float*)d_in[8];
    const float* ctl_bhh = (const float*)d_in[9];
    const float* iface_W = (const float*)d_in[10];
    const float* iface_b = (const float*)d_in[11];
    const float* out_W   = (const float*)d_in[12];
    const float* out_b   = (const float*)d_in[13];
    float* out = (float*)d_out;

    prep_kernel<<<448, 256>>>(enc_Wih, enc_Whh, enc_bih, enc_bhh,
                              ctl_Wih, ctl_Whh, ctl_bih, ctl_bhh,
                              iface_W, iface_b, out_W, out_b);

    int smem = (int)sizeof(Smem);
    cudaFuncSetAttribute(dnc_kernel, cudaFuncAttributeMaxDynamicSharedMemorySize, smem);
    dnc_kernel<<<2 * Bn, NTH, smem>>>(input, out);
}

// round 6
// speedup vs baseline: 3.1861x; 1.1844x over previous
#include <cuda_runtime.h>
#include <cstddef>
#include <cstdint>

#define Bn 32
#define Tn 256
#define Wn 128
#define Rn 4
#define Nn 128
#define IFACEn 919
#define NTH 1024
#define DELTAf 1e-6f

// -------- transposed-weight scratch + pipeline buffers (device globals) --------
__device__ float g_encT[256 * 512];    // [k][j] k = x(128)||h(128)
__device__ float g_cpreT[128 * 512];   // [k][j] h_enc -> ctl gates part
__device__ float g_ctlT[640 * 512];    // [k][j] k = rv(512, w*4+r)||h_ctl(128)
__device__ float g_ifcT[128 * 920];    // [k][j] j padded 919->920
__device__ float g_outT[640 * 128];    // [k][o] k = rv(512)||h_ctl(128)
__device__ float g_benc[512];
__device__ float g_bctl[512];
__device__ float g_bifc[920];
__device__ float g_bout[128];
__device__ float g_ctlpre[(size_t)Bn * Tn * 1024];  // per (b,t): [rank0 partial(512) | rank1 partial(512)]

__global__ void prep_kernel(
    const float* __restrict__ enc_Wih, const float* __restrict__ enc_Whh,
    const float* __restrict__ enc_bih, const float* __restrict__ enc_bhh,
    const float* __restrict__ ctl_Wih, const float* __restrict__ ctl_Whh,
    const float* __restrict__ ctl_bih, const float* __restrict__ ctl_bhh,
    const float* __restrict__ iface_W, const float* __restrict__ iface_b,
    const float* __restrict__ out_W, const float* __restrict__ out_b)
{
    const int idx = blockIdx.x * blockDim.x + threadIdx.x;
    const int stride = gridDim.x * blockDim.x;
    for (int i = idx; i < 256 * 512; i += stride) {
        int k = i >> 9, j = i & 511;
        g_encT[i] = (k < 128) ? enc_Wih[(size_t)j * 128 + k]
                              : enc_Whh[(size_t)j * 128 + (k - 128)];
    }
    for (int i = idx; i < 128 * 512; i += stride) {
        int k = i >> 9, j = i & 511;
        g_cpreT[i] = ctl_Wih[(size_t)j * 640 + 5 * k];
    }
    for (int i = idx; i < 640 * 512; i += stride) {
        int k = i >> 9, j = i & 511;
        g_ctlT[i] = (k < 512) ? ctl_Wih[(size_t)j * 640 + 5 * (k >> 2) + 1 + (k & 3)]
                              : ctl_Whh[(size_t)j * 128 + (k - 512)];
    }
    for (int i = idx; i < 128 * 920; i += stride) {
        int k = i / 920, j = i - k * 920;
        g_ifcT[i] = (j < IFACEn) ? iface_W[(size_t)j * 128 + k] : 0.f;
    }
    for (int i = idx; i < 640 * 128; i += stride) {
        int k = i >> 7, o = i & 127;
        g_outT[i] = (k < 512) ? out_W[(size_t)o * 640 + 128 + k]
                              : out_W[(size_t)o * 640 + (k - 512)];
    }
    if (idx < 512) {
        g_benc[idx] = enc_bih[idx] + enc_bhh[idx];
        g_bctl[idx] = ctl_bih[idx] + ctl_bhh[idx];
    }
    if (idx < 920) g_bifc[idx] = (idx < IFACEn) ? iface_b[idx] : 0.f;
    if (idx < 128) g_bout[idx] = out_b[idx];
}

__device__ __forceinline__ float sigm(float x) { return 1.0f / (1.0f + expf(-x)); }
__device__ __forceinline__ float softplusf(float x) {
    return (x > 0.f) ? (x + log1pf(expf(-x))) : log1pf(expf(x));
}
__device__ __forceinline__ float wsum(float v) {
    v += __shfl_xor_sync(0xffffffffu, v, 16);
    v += __shfl_xor_sync(0xffffffffu, v, 8);
    v += __shfl_xor_sync(0xffffffffu, v, 4);
    v += __shfl_xor_sync(0xffffffffu, v, 2);
    v += __shfl_xor_sync(0xffffffffu, v, 1);
    return v;
}
__device__ __forceinline__ float wmax(float v) {
    v = fmaxf(v, __shfl_xor_sync(0xffffffffu, v, 16));
    v = fmaxf(v, __shfl_xor_sync(0xffffffffu, v, 8));
    v = fmaxf(v, __shfl_xor_sync(0xffffffffu, v, 4));
    v = fmaxf(v, __shfl_xor_sync(0xffffffffu, v, 2));
    v = fmaxf(v, __shfl_xor_sync(0xffffffffu, v, 1));
    return v;
}
__device__ __forceinline__ float dot4(float4 a, float4 b) {
    return a.x * b.x + a.y * b.y + a.z * b.z + a.w * b.w;
}
__device__ __forceinline__ void dsmem_store(void* local_ptr, uint32_t peer, float v) {
    uint32_t la = (uint32_t)__cvta_generic_to_shared(local_ptr);
    uint32_t rem;
    asm volatile("mapa.shared::cluster.u32 %0, %1, %2;" : "=r"(rem) : "r"(la), "r"(peer));
    asm volatile("st.shared::cluster.f32 [%0], %1;" :: "r"(rem), "f"(v) : "memory");
}
#define CLUSTER_SYNC() do { \
    asm volatile("barrier.cluster.arrive.aligned;" ::: "memory"); \
    asm volatile("barrier.cluster.wait.aligned;" ::: "memory"); } while (0)

#define GEMV_BLK(WP, RS, K)                                                    \
    {                                                                          \
        float4 xv = *(const float4*)&xsrc[(K)];                                \
        float4 w0 = (WP)[(size_t)((K) + 0) * (RS)];                            \
        float4 w1 = (WP)[(size_t)((K) + 1) * (RS)];                            \
        float4 w2 = (WP)[(size_t)((K) + 2) * (RS)];                            \
        float4 w3 = (WP)[(size_t)((K) + 3) * (RS)];                            \
        a0.x += xv.x * w0.x; a0.y += xv.x * w0.y; a0.z += xv.x * w0.z; a0.w += xv.x * w0.w; \
        a1.x += xv.y * w1.x; a1.y += xv.y * w1.y; a1.z += xv.y * w1.z; a1.w += xv.y * w1.w; \
        a0.x += xv.z * w2.x; a0.y += xv.z * w2.y; a0.z += xv.z * w2.z; a0.w += xv.z * w2.w; \
        a1.x += xv.w * w3.x; a1.y += xv.w * w3.y; a1.z += xv.w * w3.z; a1.w += xv.w * w3.w; \
    }

// ===================== encoder kernel: 32 batches x 2-CTA cluster =====================
struct EncSmem {
    float gp[4096];
    float xs[256];
    float bufo[512];
    float pe[2][512];   // double-buffered by step parity (single rendezvous/step)
    float h[128], c[128];
};

__global__ void __launch_bounds__(NTH, 1) __cluster_dims__(2, 1, 1) enc_kernel(
    const float* __restrict__ input)
{
    extern __shared__ char smraw[];
    EncSmem* s = reinterpret_cast<EncSmem*>(smraw);
    const int b = blockIdx.x >> 1;
    const uint32_t rank = blockIdx.x & 1;
    const uint32_t peer = rank ^ 1;
    const int tid = threadIdx.x;

    if (tid < 128) { s->h[tid] = 0.f; s->c[tid] = 0.f; }
    __syncthreads();

    for (int t = 0; t < Tn; ++t) {
        if (tid < 128) {
            s->xs[tid] = input[((size_t)b * Tn + t) * Wn + tid];
            s->xs[128 + tid] = s->h[tid];
        }
        __syncthreads();
        {   // gates GEMV: 256k (split 128/rank) x 512j
            const int u = tid & 127, kc = tid >> 7;
            const float4* wp = ((const float4*)g_encT) + u;
            const float* xsrc = s->xs;
            float4 a0 = make_float4(0, 0, 0, 0), a1 = a0;
            const int k0 = (int)rank * 128 + kc * 16;
#pragma unroll
            for (int kk = 0; kk < 16; kk += 4) GEMV_BLK(wp, 128, k0 + kk);
            ((float4*)s->gp)[kc * 128 + u] =
                make_float4(a0.x + a1.x, a0.y + a1.y, a0.z + a1.z, a0.w + a1.w);
        }
        __syncthreads();
        if (tid < 512) {
            float p = 0.f;
#pragma unroll
            for (int kc = 0; kc < 8; ++kc) p += s->gp[kc * 512 + tid];
            s->bufo[tid] = p;
            dsmem_store(&s->pe[t & 1][tid], peer, p);
        }
        CLUSTER_SYNC();
        if (tid < 128) {
            const float* pe = s->pe[t & 1];
            float gi = sigm(s->bufo[tid]       + pe[tid]       + g_benc[tid]);
            float gf = sigm(s->bufo[128 + tid] + pe[128 + tid] + g_benc[128 + tid]);
            float gg = tanhf(s->bufo[256 + tid] + pe[256 + tid] + g_benc[256 + tid]);
            float go = sigm(s->bufo[384 + tid] + pe[384 + tid] + g_benc[384 + tid]);
            float c = gf * s->c[tid] + gi * gg;
            s->c[tid] = c;
            s->h[tid] = go * tanhf(c);
        }
        __syncthreads();
        {   // ctl_pre partial GEMV: 128k (split 64/rank) x 512j, x = h
            const int u = tid & 127, kc = tid >> 7;
            const float4* wp = ((const float4*)g_cpreT) + u;
            const float* xsrc = s->h;
            float4 a0 = make_float4(0, 0, 0, 0), a1 = a0;
            const int k0 = (int)rank * 64 + kc * 8;
#pragma unroll
            for (int kk = 0; kk < 8; kk += 4) GEMV_BLK(wp, 128, k0 + kk);
            ((float4*)s->gp)[kc * 128 + u] =
                make_float4(a0.x + a1.x, a0.y + a1.y, a0.z + a1.z, a0.w + a1.w);
        }
        __syncthreads();
        if (tid < 512) {   // each rank writes its OWN slot -> no exchange needed
            float p = 0.f;
#pragma unroll
            for (int kc = 0; kc < 8; ++kc) p += s->gp[kc * 512 + tid];
            g_ctlpre[((size_t)b * Tn + t) * 1024 + rank * 512 + tid] = p;
        }
        __syncthreads();
    }
}

// ===================== DNC kernel: 32 batches x 2-CTA cluster =====================
struct Smem {
    float mem[Nn][Wn];     // 64KB
    float lnk[Nn][Nn];     // 64KB
    float gp[4096];        // GEMV partials (16KB)
    float xs[640];         // shared GEMV input: [rv(512, w*4+r) | h_ctl(128)]
    float bufo[920];       // local GEMV reduced partial
    float pc[512];         // peer partials (distinct per GEMV; rendezvous-ordered)
    float pi[920];
    float po[128];
    float c_ctl[Wn];
    float rw[Rn * Nn];
    float rwn[Rn * Nn];
    float ww[Nn];
    float prec[2][Nn];
    float usage[Nn];
    float rk[Rn][Wn];
    float wk[Wn];
    float er[Wn];
    float wv[Wn];
    float rstr[Rn];
    float fg[Rn];
    float rknorm[Rn];
    float rm[Rn][3];
    float xmraw[12];
    float wc[Nn];
    float uu[Nn];
    float psu[Nn];
    float nrm[Nn];
    float rc[Rn][Nn];
    float fwv[Rn][Nn];
    float red[32];
    float scal[8];   // 0:wstr 1:ag 2:wg 3:wknorm
    int   rnk[Nn];
};

__global__ void __launch_bounds__(NTH, 1) __cluster_dims__(2, 1, 1) dnc_kernel(
    float* __restrict__ out)
{
    extern __shared__ char smraw[];
    Smem* s = reinterpret_cast<Smem*>(smraw);
    const int tid = threadIdx.x;
    const int wid = tid >> 5;
    const int lane = tid & 31;
    const int b = blockIdx.x >> 1;
    const uint32_t rank = blockIdx.x & 1;
    const uint32_t peer = rank ^ 1;
    const float* __restrict__ cpre_base = g_ctlpre + (size_t)b * Tn * 1024;

    // ---- zero recurrent state ----
    {
        float* p = &s->mem[0][0];   // mem + lnk contiguous
        for (int i = tid; i < Nn * Wn + Nn * Nn; i += NTH) p[i] = 0.f;
        if (tid < Wn) {
            s->c_ctl[tid] = 0.f; s->ww[tid] = 0.f;
            s->prec[0][tid] = 0.f; s->usage[tid] = 0.f;
        }
        if (tid < 640) s->xs[tid] = 0.f;
        if (tid < 512) s->rw[tid] = 0.f;
    }
    __syncthreads();

    for (int t = 0; t < Tn; ++t) {
        const int pcur = t & 1, pnxt = pcur ^ 1;
        // ===== ctl GEMV: 640k (split 320) x 512j, x = xs =====
        {
            const int u = tid & 127, kc = tid >> 7;   // 8 chunks x 40 k
            const float4* wp = ((const float4*)g_ctlT) + u;
            const float* xsrc = s->xs;
            float4 a0 = make_float4(0, 0, 0, 0), a1 = a0;
            const int k0 = (int)rank * 320 + kc * 40;
#pragma unroll
            for (int kk = 0; kk < 40; kk += 4) GEMV_BLK(wp, 128, k0 + kk);
            ((float4*)s->gp)[kc * 128 + u] =
                make_float4(a0.x + a1.x, a0.y + a1.y, a0.z + a1.z, a0.w + a1.w);
        }
        __syncthreads();
        if (tid < 512) {
            float p = 0.f;
#pragma unroll
            for (int kc = 0; kc < 8; ++kc) p += s->gp[kc * 512 + tid];
            s->bufo[tid] = p;
            dsmem_store(&s->pc[tid], peer, p);
        }
        CLUSTER_SYNC();
        // ctl cell: local + peer + both precomputed enc partials + bias
        if (tid < Wn) {
            const float* cp = cpre_base + (size_t)t * 1024;
            float gi = s->bufo[tid]       + s->pc[tid]       + cp[tid]       + cp[512 + tid] + g_bctl[tid];
            float gf = s->bufo[128 + tid] + s->pc[128 + tid] + cp[128 + tid] + cp[640 + tid] + g_bctl[128 + tid];
            float gg = s->bufo[256 + tid] + s->pc[256 + tid] + cp[256 + tid] + cp[768 + tid] + g_bctl[256 + tid];
            float go = s->bufo[384 + tid] + s->pc[384 + tid] + cp[384 + tid] + cp[896 + tid] + g_bctl[384 + tid];
            gi = sigm(gi); gf = sigm(gf); gg = tanhf(gg); go = sigm(go);
            float c = gf * s->c_ctl[tid] + gi * gg;
            s->c_ctl[tid] = c;
            s->xs[512 + tid] = go * tanhf(c);   // h_ctl lives in xs[512..639]
        }
        __syncthreads();

        // ===== iface GEMV: 128k (split 64) x 920j, x = h_ctl =====
        if (tid < 920) {
            const int kc = tid / 230, u = tid - kc * 230;  // 4 chunks x 16 k
            const float4* wp = ((const float4*)g_ifcT) + u;
            const float* xsrc = s->xs + 512;
            float4 a0 = make_float4(0, 0, 0, 0), a1 = a0;
            const int k0 = (int)rank * 64 + kc * 16;
#pragma unroll
            for (int kk = 0; kk < 16; kk += 4) GEMV_BLK(wp, 230, k0 + kk);
            ((float4*)(s->gp + kc * 920))[u] =
                make_float4(a0.x + a1.x, a0.y + a1.y, a0.z + a1.z, a0.w + a1.w);
        }
        __syncthreads();
        if (tid < 920) {
            float p = s->gp[tid] + s->gp[920 + tid] + s->gp[1840 + tid] + s->gp[2760 + tid];
            s->bufo[tid] = p;
            dsmem_store(&s->pi[tid], peer, p);
        }
        CLUSTER_SYNC();
        // ===== xi combine + parse (fused, elementwise by range) =====
        if (tid < IFACEn) {
            int j = tid;
            float v = s->bufo[j] + s->pi[j] + g_bifc[j];
            if (j < 512)       ((float*)s->rk)[j] = tanhf(v);
            else if (j < 516)  s->rstr[j - 512] = softplusf(v);
            else if (j < 644)  s->wk[j - 516] = tanhf(v);
            else if (j == 644) s->scal[0] = softplusf(v);
            else if (j < 773)  s->er[j - 645] = sigm(v);
            else if (j < 901)  s->wv[j - 773] = tanhf(v);
            else if (j < 905)  s->fg[j - 901] = sigm(v);
            else if (j == 905) s->scal[1] = sigm(v);
            else if (j == 906) s->scal[2] = sigm(v);
            else               s->xmraw[j - 907] = v;
        }
        __syncthreads();

        // ===== usage update + uu + wk norm + old-mem norms & wk dots =====
        if (tid < Nn) {
            float us = s->usage[tid];
            us = us + (1.f - us) * s->ww[tid];
            float ret = 1.f;
#pragma unroll
            for (int r = 0; r < Rn; ++r) ret *= (1.f - s->fg[r] * s->rw[r * Nn + tid]);
            us *= ret;
            s->usage[tid] = us;
            s->uu[tid] = DELTAf + (1.f - DELTAf) * us;
        }
        {
            float4 k4 = ((const float4*)s->wk)[lane];
            if (wid == 0) {
                float nv = wsum(dot4(k4, k4));
                if (lane == 0) s->scal[3] = sqrtf(nv);
            }
#pragma unroll
            for (int rr = 0; rr < 4; ++rr) {
                int n = wid * 4 + rr;
                float4 m4 = ((const float4*)s->mem[n])[lane];
                float dn = wsum(dot4(m4, m4));
                float dk = wsum(dot4(m4, k4));
                if (lane == 0) { s->nrm[n] = sqrtf(dn); s->wc[n] = dk; }
            }
        }
        __syncthreads();

        // ===== P1: {rank+scan (warps 0-3 + named bar)} || {wc softmax (warp 8)} || {rm (warp 5)} =====
        if (tid < Nn) {
            float un = s->uu[tid];
            int rk_ = 0;
#pragma unroll 8
            for (int j = 0; j < Nn; ++j) {
                float uj = s->uu[j];
                rk_ += (uj < un) || (uj == un && j < tid);
            }
            s->rnk[tid] = rk_;
            s->psu[rk_] = un;
            asm volatile("bar.sync 1, 128;" ::: "memory");
            if (wid == 0) {   // inclusive cumprod scan of psu
                float v0 = s->psu[lane * 4], v1 = s->psu[lane * 4 + 1];
                float v2 = s->psu[lane * 4 + 2], v3 = s->psu[lane * 4 + 3];
                float l1 = v0 * v1, l2 = l1 * v2, l3 = l2 * v3;
                float run = l3;
#pragma unroll
                for (int off = 1; off < 32; off <<= 1) {
                    float up = __shfl_up_sync(0xffffffffu, run, off);
                    if (lane >= off) run *= up;
                }
                float ex = __shfl_up_sync(0xffffffffu, run, 1);
                if (lane == 0) ex = 1.f;
                s->psu[lane * 4]     = ex * v0;
                s->psu[lane * 4 + 1] = ex * l1;
                s->psu[lane * 4 + 2] = ex * l2;
                s->psu[lane * 4 + 3] = ex * l3;
            }
        } else if (wid == 8) {   // write-content softmax, fully in-warp
            float inw = 1.f / ((s->scal[3] + DELTAf));
            float ws = s->scal[0];
            float v[4];
            float mx = -1e30f;
#pragma unroll
            for (int q = 0; q < 4; ++q) {
                int n = lane + 32 * q;
                v[q] = s->wc[n] / (s->nrm[n] + DELTAf) * inw * ws;
                mx = fmaxf(mx, v[q]);
            }
            mx = wmax(mx);
            float sm = 0.f;
#pragma unroll
            for (int q = 0; q < 4; ++q) { v[q] = expf(v[q] - mx); sm += v[q]; }
            sm = wsum(sm);
            float inv = 1.f / sm;
#pragma unroll
            for (int q = 0; q < 4; ++q) s->wc[lane + 32 * q] = v[q] * inv;
        } else if (wid == 5 && lane < Rn) {   // read-modes 3-way softmax
            int r = lane;
            float a = s->xmraw[r * 3], b2 = s->xmraw[r * 3 + 1], c2 = s->xmraw[r * 3 + 2];
            float m = fmaxf(a, fmaxf(b2, c2));
            float ea = expf(a - m), eb = expf(b2 - m), ec = expf(c2 - m);
            float inv = 1.f / (ea + eb + ec);
            s->rm[r][0] = ea * inv; s->rm[r][1] = eb * inv; s->rm[r][2] = ec * inv;
        }
        __syncthreads();

        // ===== P3: alloc + new write weighting + warp partial sums =====
        if (tid < Nn) {
            int r_ = s->rnk[tid];
            float excl = (r_ == 0) ? 1.f : s->psu[r_ - 1];
            float alloc = (1.f - s->uu[tid]) * excl;
            float ag = s->scal[1], wg = s->scal[2];
            float v = wg * (ag * alloc + (1.f - ag) * s->wc[tid]);
            s->ww[tid] = v;
            float sm = wsum(v);
            if (lane == 0) s->red[wid] = sm;
        }
        __syncthreads();

        // ===== P4: mem erase+write, link update (reads prec[pcur]) + sum_ww/new prec =====
        {
            float4* m4 = (float4*)s->mem;
            const float4* e4p = (const float4*)s->er;
            const float4* v4p = (const float4*)s->wv;
#pragma unroll
            for (int it = 0; it < 4; ++it) {
                int idx = tid + it * NTH;
                int n = idx >> 5, q = idx & 31;
                float wwn = s->ww[n];
                float4 m = m4[idx], e = e4p[q], v = v4p[q];
                m.x = m.x * (1.f - wwn * e.x) + wwn * v.x;
                m.y = m.y * (1.f - wwn * e.y) + wwn * v.y;
                m.z = m.z * (1.f - wwn * e.z) + wwn * v.z;
                m.w = m.w * (1.f - wwn * e.w) + wwn * v.w;
                m4[idx] = m;
            }
            float4* l4 = (float4*)s->lnk;
            const float4* wwp = (const float4*)s->ww;
            const float4* pcp = (const float4*)s->prec[pcur];
#pragma unroll
            for (int it = 0; it < 4; ++it) {
                int idx = tid + it * NTH;
                int i = idx >> 5, q = idx & 31;
                float wwi = s->ww[i];
                float4 L = l4[idx], wj = wwp[q], pj = pcp[q];
                L.x = (1.f - wwi - wj.x) * L.x + wwi * pj.x;
                L.y = (1.f - wwi - wj.y) * L.y + wwi * pj.y;
                L.z = (1.f - wwi - wj.z) * L.z + wwi * pj.z;
                L.w = (1.f - wwi - wj.w) * L.w + wwi * pj.w;
                if ((i >> 2) == q) ((float*)&L)[i & 3] = 0.f;
                l4[idx] = L;
            }
            if (wid == 31) {
                float v = (lane < 4) ? s->red[lane] : 0.f;
                float sw = wsum(v);
#pragma unroll
                for (int q = 0; q < 4; ++q) {
                    int n = lane + 32 * q;
                    s->prec[pnxt][n] = (1.f - sw) * s->prec[pcur][n] + s->ww[n];
                }
            }
        }
        __syncthreads();

        // ===== P5: new-mem norms & read-key dots + read-key norms =====
        {
            float4 k0 = ((const float4*)s->rk[0])[lane];
            float4 k1 = ((const float4*)s->rk[1])[lane];
            float4 k2 = ((const float4*)s->rk[2])[lane];
            float4 k3 = ((const float4*)s->rk[3])[lane];
#pragma unroll
            for (int rr = 0; rr < 4; ++rr) {
                int n = wid * 4 + rr;
                float4 m = ((const float4*)s->mem[n])[lane];
                float dn = wsum(dot4(m, m));
                float d0 = wsum(dot4(m, k0));
                float d1 = wsum(dot4(m, k1));
                float d2 = wsum(dot4(m, k2));
                float d3 = wsum(dot4(m, k3));
                if (lane == 0) {
                    s->nrm[n] = sqrtf(dn);
                    s->rc[0][n] = d0; s->rc[1][n] = d1; s->rc[2][n] = d2; s->rc[3][n] = d3;
                }
            }
            if (wid < Rn) {
                float4 k4 = ((const float4*)s->rk[wid])[lane];
                float nv = wsum(dot4(k4, k4));
                if (lane == 0) s->rknorm[wid] = sqrtf(nv);
            }
        }
        __syncthreads();

        // ===== P6: {read softmax (warps 0-3, in-warp)} || {fw row-dots (warps 4-31)} =====
        if (wid < Rn) {
            int r_ = wid;
            float inv_kn = 1.f / (s->rknorm[r_] + DELTAf);
            float rs = s->rstr[r_];
            float v[4];
            float mx = -1e30f;
#pragma unroll
            for (int q = 0; q < 4; ++q) {
                int n = lane + 32 * q;
                v[q] = s->rc[r_][n] / (s->nrm[n] + DELTAf) * inv_kn * rs;
                mx = fmaxf(mx, v[q]);
            }
            mx = wmax(mx);
            float sm = 0.f;
#pragma unroll
            for (int q = 0; q < 4; ++q) { v[q] = expf(v[q] - mx); sm += v[q]; }
            sm = wsum(sm);
            float inv = 1.f / sm;
#pragma unroll
            for (int q = 0; q < 4; ++q) s->rc[r_][lane + 32 * q] = v[q] * inv;
        } else {
            float4 w0 = ((const float4*)s->rw)[lane];
            float4 w1 = ((const float4*)s->rw)[32 + lane];
            float4 w2 = ((const float4*)s->rw)[64 + lane];
            float4 w3 = ((const float4*)s->rw)[96 + lane];
            for (int i = wid - 4; i < Nn; i += 28) {
                float4 L = ((const float4*)s->lnk[i])[lane];
                float d0 = wsum(dot4(L, w0));
                float d1 = wsum(dot4(L, w1));
                float d2 = wsum(dot4(L, w2));
                float d3 = wsum(dot4(L, w3));
                if (lane == 0) {
                    s->fwv[0][i] = d0; s->fwv[1][i] = d1;
                    s->fwv[2][i] = d2; s->fwv[3][i] = d3;
                }
            }
        }
        __syncthreads();

        // ===== P7: bw column-dot + combine read modes -> rwn =====
        if (tid < 512) {
            int r_ = tid >> 7, i = tid & 127;
            const float* rwr = s->rw + r_ * Nn;
            float acc = 0.f;
#pragma unroll 4
            for (int j = 0; j < Nn; ++j)
                acc += rwr[j] * s->lnk[j][i];
            s->rwn[tid] = s->rm[r_][0] * acc
                        + s->rm[r_][1] * s->fwv[r_][i]
                        + s->rm[r_][2] * s->rc[r_][i];
        }
        __syncthreads();

        // ===== P8: read vectors -> xs[rv], commit rw =====
        if (tid < 512) {
            int r_ = tid >> 7, w = tid & 127;
            const float* rwn_r = s->rwn + r_ * Nn;
            float acc = 0.f;
#pragma unroll 4
            for (int n = 0; n < Nn; ++n)
                acc += rwn_r[n] * s->mem[n][w];
            s->xs[w * 4 + r_] = acc;
            s->rw[tid] = s->rwn[tid];
        }
        __syncthreads();

        // ===== out GEMV: 640k (split 320) x 128o, x = xs =====
        if (tid < 512) {
            const int u = tid & 31, kc = tid >> 5;   // 16 chunks x 20 k
            const float4* wp = ((const float4*)g_outT) + u;
            const float* xsrc = s->xs;
            float4 a0 = make_float4(0, 0, 0, 0), a1 = a0;
            const int k0 = (int)rank * 320 + kc * 20;
#pragma unroll
            for (int kk = 0; kk < 20; kk += 4) GEMV_BLK(wp, 32, k0 + kk);
            ((float4*)s->gp)[kc * 32 + u] =
                make_float4(a0.x + a1.x, a0.y + a1.y, a0.z + a1.z, a0.w + a1.w);
        }
        __syncthreads();
        if (tid < 128) {
            float p = 0.f;
#pragma unroll
            for (int kc = 0; kc < 16; ++kc) p += s->gp[kc * 128 + tid];
            s->bufo[tid] = p;
            dsmem_store(&s->po[tid], peer, p);
        }
        CLUSTER_SYNC();
        if (rank == 0 && tid < Wn)
            out[((size_t)b * Tn + t) * Wn + tid] = s->bufo[tid] + s->po[tid] + g_bout[tid];
        __syncthreads();
    }
}

extern "C" void kernel_launch(void* const* d_in, const int* in_sizes, int n_in,
                              void* d_out, int out_size) {
    const float* input   = (const float*)d_in[0];
    // d_in[1] = source_lengths (all == T, unused)
    const float* enc_Wih = (const float*)d_in[2];
    const float* enc_Whh = (const float*)d_in[3];
    const float* enc_bih = (const float*)d_in[4];
    const float* enc_bhh = (const float*)d_in[5];
    const float* ctl_Wih = (const float*)d_in[6];
    const float* ctl_Whh = (const float*)d_in[7];
    const float* ctl_bih = (const float*)d_in[8];
    const float* ctl_bhh = (const float*)d_in[9];
    const float* iface_W = (const float*)d_in[10];
    const float* iface_b = (const float*)d_in[11];
    const float* out_W   = (const float*)d_in[12];
    const float* out_b   = (const float*)d_in[13];
    float* out = (float*)d_out;

    prep_kernel<<<448, 256>>>(enc_Wih, enc_Whh, enc_bih, enc_bhh,
                              ctl_Wih, ctl_Whh, ctl_bih, ctl_bhh,
                              iface_W, iface_b, out_W, out_b);

    int esm = (int)sizeof(EncSmem);
    cudaFuncSetAttribute(enc_kernel, cudaFuncAttributeMaxDynamicSharedMemorySize, esm);
    enc_kernel<<<2 * Bn, NTH, esm>>>(input);

    int smem = (int)sizeof(Smem);
    cudaFuncSetAttribute(dnc_kernel, cudaFuncAttributeMaxDynamicSharedMemorySize, smem);
    dnc_kernel<<<2 * Bn, NTH, smem>>>(out);
}

// round 7
// speedup vs baseline: 3.4539x; 1.0840x over previous
#include <cuda_runtime.h>
#include <cstddef>
#include <cstdint>

#define Bn 32
#define Tn 256
#define Wn 128
#define Rn 4
#define Nn 128
#define IFACEn 919
#define NTH 1024
#define DELTAf 1e-6f

typedef unsigned long long ull;

// -------- transposed-weight scratch + pipeline buffers (device globals) --------
__device__ float g_encT[256 * 512];    // [k][j] k = x(128)||h(128)
__device__ float g_cpreT[128 * 512];   // [k][j] h_enc -> ctl gates part
__device__ float g_cboT[640 * 640];    // [k][j] k = rv(512, w*4+r)||h_ctl(128); j = gates(512)||out(128)
__device__ float g_ifcT[128 * 920];    // [k][j] j padded 919->920
__device__ float g_benc[512];
__device__ float g_bctl[512];
__device__ float g_bifc[920];
__device__ float g_bout[128];
__device__ float g_ctlpre[(size_t)Bn * Tn * 1024];  // per (b,t): [rank0 partial(512) | rank1 partial(512)]

__global__ void prep_kernel(
    const float* __restrict__ enc_Wih, const float* __restrict__ enc_Whh,
    const float* __restrict__ enc_bih, const float* __restrict__ enc_bhh,
    const float* __restrict__ ctl_Wih, const float* __restrict__ ctl_Whh,
    const float* __restrict__ ctl_bih, const float* __restrict__ ctl_bhh,
    const float* __restrict__ iface_W, const float* __restrict__ iface_b,
    const float* __restrict__ out_W, const float* __restrict__ out_b)
{
    const int idx = blockIdx.x * blockDim.x + threadIdx.x;
    const int stride = gridDim.x * blockDim.x;
    for (int i = idx; i < 256 * 512; i += stride) {
        int k = i >> 9, j = i & 511;
        g_encT[i] = (k < 128) ? enc_Wih[(size_t)j * 128 + k]
                              : enc_Whh[(size_t)j * 128 + (k - 128)];
    }
    for (int i = idx; i < 128 * 512; i += stride) {
        int k = i >> 9, j = i & 511;
        g_cpreT[i] = ctl_Wih[(size_t)j * 640 + 5 * k];
    }
    for (int i = idx; i < 640 * 640; i += stride) {
        int k = i / 640, j = i - k * 640;
        float v;
        if (j < 512) {
            v = (k < 512) ? ctl_Wih[(size_t)j * 640 + 5 * (k >> 2) + 1 + (k & 3)]
                          : ctl_Whh[(size_t)j * 128 + (k - 512)];
        } else {
            int o = j - 512;
            v = (k < 512) ? out_W[(size_t)o * 640 + 128 + k]
                          : out_W[(size_t)o * 640 + (k - 512)];
        }
        g_cboT[i] = v;
    }
    for (int i = idx; i < 128 * 920; i += stride) {
        int k = i / 920, j = i - k * 920;
        g_ifcT[i] = (j < IFACEn) ? iface_W[(size_t)j * 128 + k] : 0.f;
    }
    if (idx < 512) {
        g_benc[idx] = enc_bih[idx] + enc_bhh[idx];
        g_bctl[idx] = ctl_bih[idx] + ctl_bhh[idx];
    }
    if (idx < 920) g_bifc[idx] = (idx < IFACEn) ? iface_b[idx] : 0.f;
    if (idx < 128) g_bout[idx] = out_b[idx];
}

__device__ __forceinline__ float sigm(float x) { return 1.0f / (1.0f + expf(-x)); }
__device__ __forceinline__ float softplusf(float x) {
    return (x > 0.f) ? (x + log1pf(expf(-x))) : log1pf(expf(x));
}
__device__ __forceinline__ float wsum(float v) {
    v += __shfl_xor_sync(0xffffffffu, v, 16);
    v += __shfl_xor_sync(0xffffffffu, v, 8);
    v += __shfl_xor_sync(0xffffffffu, v, 4);
    v += __shfl_xor_sync(0xffffffffu, v, 2);
    v += __shfl_xor_sync(0xffffffffu, v, 1);
    return v;
}
__device__ __forceinline__ float wmax(float v) {
    v = fmaxf(v, __shfl_xor_sync(0xffffffffu, v, 16));
    v = fmaxf(v, __shfl_xor_sync(0xffffffffu, v, 8));
    v = fmaxf(v, __shfl_xor_sync(0xffffffffu, v, 4));
    v = fmaxf(v, __shfl_xor_sync(0xffffffffu, v, 2));
    v = fmaxf(v, __shfl_xor_sync(0xffffffffu, v, 1));
    return v;
}
__device__ __forceinline__ float dot4(float4 a, float4 b) {
    return a.x * b.x + a.y * b.y + a.z * b.z + a.w * b.w;
}
__device__ __forceinline__ void fma2(ull& acc, ull w, ull x) {
    asm("fma.rn.f32x2 %0, %1, %2, %0;" : "+l"(acc) : "l"(w), "l"(x));
}
__device__ __forceinline__ ull packf2(float x) {
    ull r; asm("mov.b64 %0, {%1, %1};" : "=l"(r) : "f"(x)); return r;
}
__device__ __forceinline__ float2 unpackf2(ull v) {
    float2 r; asm("mov.b64 {%0, %1}, %2;" : "=f"(r.x), "=f"(r.y) : "l"(v)); return r;
}
__device__ __forceinline__ float4 comb4(ull aL0, ull aH0, ull aL1, ull aH1) {
    float2 l0 = unpackf2(aL0), h0 = unpackf2(aH0), l1 = unpackf2(aL1), h1 = unpackf2(aH1);
    return make_float4(l0.x + l1.x, l0.y + l1.y, h0.x + h1.x, h0.y + h1.y);
}
__device__ __forceinline__ void dsmem_store(void* local_ptr, uint32_t peer, float v) {
    uint32_t la = (uint32_t)__cvta_generic_to_shared(local_ptr);
    uint32_t rem;
    asm volatile("mapa.shared::cluster.u32 %0, %1, %2;" : "=r"(rem) : "r"(la), "r"(peer));
    asm volatile("st.shared::cluster.f32 [%0], %1;" :: "r"(rem), "f"(v) : "memory");
}
#define CLUSTER_SYNC() do { \
    asm volatile("barrier.cluster.arrive.aligned;" ::: "memory"); \
    asm volatile("barrier.cluster.wait.aligned;" ::: "memory"); } while (0)

// f32x2 GEMV block: 4 k's, 4 LDG.128 weight loads, 8 FFMA2 (accs aL0,aH0,aL1,aH1; xsrc float4-aligned at K)
#define GEMV_BLK2(WP, RS, K)                                                   \
    {                                                                          \
        float4 xv = *(const float4*)&xsrc[(K)];                                \
        ulonglong2 w0 = (WP)[(size_t)((K) + 0) * (RS)];                        \
        ulonglong2 w1 = (WP)[(size_t)((K) + 1) * (RS)];                        \
        ulonglong2 w2 = (WP)[(size_t)((K) + 2) * (RS)];                        \
        ulonglong2 w3 = (WP)[(size_t)((K) + 3) * (RS)];                        \
        ull x0 = packf2(xv.x), x1 = packf2(xv.y), x2 = packf2(xv.z), x3 = packf2(xv.w); \
        fma2(aL0, w0.x, x0); fma2(aH0, w0.y, x0);                              \
        fma2(aL1, w1.x, x1); fma2(aH1, w1.y, x1);                              \
        fma2(aL0, w2.x, x2); fma2(aH0, w2.y, x2);                              \
        fma2(aL1, w3.x, x3); fma2(aH1, w3.y, x3);                              \
    }

// ===================== encoder kernel: 32 batches x 2-CTA cluster =====================
struct EncSmem {
    float gp[4096];
    float xs[256];
    float bufo[512];
    float pe[2][512];   // double-buffered by step parity
    float h[128], c[128];
};

__global__ void __launch_bounds__(NTH, 1) __cluster_dims__(2, 1, 1) enc_kernel(
    const float* __restrict__ input)
{
    extern __shared__ char smraw[];
    EncSmem* s = reinterpret_cast<EncSmem*>(smraw);
    const int b = blockIdx.x >> 1;
    const uint32_t rank = blockIdx.x & 1;
    const uint32_t peer = rank ^ 1;
    const int tid = threadIdx.x;

    if (tid < 128) { s->h[tid] = 0.f; s->c[tid] = 0.f; }
    __syncthreads();

    for (int t = 0; t < Tn; ++t) {
        if (tid < 128) {
            s->xs[tid] = input[((size_t)b * Tn + t) * Wn + tid];
            s->xs[128 + tid] = s->h[tid];
        }
        __syncthreads();
        {   // gates GEMV: 256k (split 128/rank) x 512j
            const int u = tid & 127, kc = tid >> 7;
            const ulonglong2* wp = ((const ulonglong2*)g_encT) + u;
            const float* xsrc = s->xs;
            ull aL0 = 0, aH0 = 0, aL1 = 0, aH1 = 0;
            const int k0 = (int)rank * 128 + kc * 16;
#pragma unroll
            for (int kk = 0; kk < 16; kk += 4) GEMV_BLK2(wp, 128, k0 + kk);
            ((float4*)s->gp)[kc * 128 + u] = comb4(aL0, aH0, aL1, aH1);
        }
        __syncthreads();
        if (tid < 512) {
            float p = 0.f;
#pragma unroll
            for (int kc = 0; kc < 8; ++kc) p += s->gp[kc * 512 + tid];
            s->bufo[tid] = p;
            dsmem_store(&s->pe[t & 1][tid], peer, p);
        }
        CLUSTER_SYNC();
        if (tid < 128) {
            const float* pe = s->pe[t & 1];
            float gi = sigm(s->bufo[tid]       + pe[tid]       + g_benc[tid]);
            float gf = sigm(s->bufo[128 + tid] + pe[128 + tid] + g_benc[128 + tid]);
            float gg = tanhf(s->bufo[256 + tid] + pe[256 + tid] + g_benc[256 + tid]);
            float go = sigm(s->bufo[384 + tid] + pe[384 + tid] + g_benc[384 + tid]);
            float c = gf * s->c[tid] + gi * gg;
            s->c[tid] = c;
            s->h[tid] = go * tanhf(c);
        }
        __syncthreads();
        {   // ctl_pre partial GEMV: 128k (split 64/rank) x 512j, x = h
            const int u = tid & 127, kc = tid >> 7;
            const ulonglong2* wp = ((const ulonglong2*)g_cpreT) + u;
            const float* xsrc = s->h;
            ull aL0 = 0, aH0 = 0, aL1 = 0, aH1 = 0;
            const int k0 = (int)rank * 64 + kc * 8;
#pragma unroll
            for (int kk = 0; kk < 8; kk += 4) GEMV_BLK2(wp, 128, k0 + kk);
            ((float4*)s->gp)[kc * 128 + u] = comb4(aL0, aH0, aL1, aH1);
        }
        __syncthreads();
        if (tid < 512) {   // each rank writes its OWN slot -> no exchange needed
            float p = 0.f;
#pragma unroll
            for (int kc = 0; kc < 8; ++kc) p += s->gp[kc * 512 + tid];
            g_ctlpre[((size_t)b * Tn + t) * 1024 + rank * 512 + tid] = p;
        }
        __syncthreads();
    }
}

// ===================== DNC kernel: 32 batches x 2-CTA cluster =====================
struct Smem {
    float mem[Nn][Wn];     // 64KB
    float lnk[Nn][Nn];     // 64KB
    float gp[8192];        // GEMV / dot partials (32KB)
    float xs[640];         // shared GEMV input: [rv(512, w*4+r) | h_ctl(128)]
    float bufo[920];       // local GEMV reduced partial (gates+out: 640; iface: 920)
    float pc[640];         // peer partials ctl+out
    float pi[920];         // peer partials iface
    float c_ctl[Wn];
    float rw[Rn * Nn];
    float rwn[Rn * Nn];
    float ww[Nn];
    float prec[2][Nn];
    float usage[Nn];
    float rk[Rn][Wn];
    float wk[Wn];
    float er[Wn];
    float wv[Wn];
    float rstr[Rn];
    float fg[Rn];
    float rknorm[Rn];
    float rm[Rn][3];
    float xmraw[12];
    float wc[Nn];
    float uu[Nn];
    float psu[Nn];
    float nrm[Nn];
    float rc[Rn][Nn];
    float fwv[Rn][Nn];
    float red[32];
    float scal[8];   // 0:wstr 1:ag 2:wg 3:wknorm
    int   rnk[Nn];
};

__global__ void __launch_bounds__(NTH, 1) __cluster_dims__(2, 1, 1) dnc_kernel(
    float* __restrict__ out)
{
    extern __shared__ char smraw[];
    Smem* s = reinterpret_cast<Smem*>(smraw);
    const int tid = threadIdx.x;
    const int wid = tid >> 5;
    const int lane = tid & 31;
    const int b = blockIdx.x >> 1;
    const uint32_t rank = blockIdx.x & 1;
    const uint32_t peer = rank ^ 1;
    const float* __restrict__ cpre_base = g_ctlpre + (size_t)b * Tn * 1024;

    // ---- zero recurrent state ----
    {
        float* p = &s->mem[0][0];   // mem + lnk contiguous
        for (int i = tid; i < Nn * Wn + Nn * Nn; i += NTH) p[i] = 0.f;
        if (tid < Wn) {
            s->c_ctl[tid] = 0.f; s->ww[tid] = 0.f;
            s->prec[0][tid] = 0.f; s->usage[tid] = 0.f;
        }
        if (tid < 640) s->xs[tid] = 0.f;
        if (tid < 512) s->rw[tid] = 0.f;
    }
    __syncthreads();

    for (int t = 0; t <= Tn; ++t) {
        // ===== fused ctl-gates + out GEMV: x = xs (state after step t-1) =====
        {
            // gates: 640k (split 320/rank) x 512j
            const int u = tid & 127, kc = tid >> 7;   // 8 chunks x 40 k
            const ulonglong2* wp = ((const ulonglong2*)g_cboT) + u;
            const float* xsrc = s->xs;
            ull aL0 = 0, aH0 = 0, aL1 = 0, aH1 = 0;
            const int k0 = (int)rank * 320 + kc * 40;
#pragma unroll
            for (int kk = 0; kk < 40; kk += 4) GEMV_BLK2(wp, 160, k0 + kk);
            ((float4*)s->gp)[kc * 128 + u] = comb4(aL0, aH0, aL1, aH1);
            // out: 640k (split 320/rank) x 128j (j-groups 128..159), 2-k granular (k0o may be %4==2)
            const int u2 = tid & 31, kc2 = tid >> 5;  // 32 chunks x 10 k
            const ulonglong2* wp2 = ((const ulonglong2*)g_cboT) + 128 + u2;
            ull bL0 = 0, bH0 = 0, bL1 = 0, bH1 = 0;
            const int k0o = (int)rank * 320 + kc2 * 10;
#pragma unroll
            for (int kk = 0; kk < 10; kk += 2) {
                float2 xv2 = *(const float2*)&xsrc[k0o + kk];
                ulonglong2 w0 = wp2[(size_t)(k0o + kk) * 160];
                ulonglong2 w1 = wp2[(size_t)(k0o + kk + 1) * 160];
                ull x0 = packf2(xv2.x), x1 = packf2(xv2.y);
                fma2(bL0, w0.x, x0); fma2(bH0, w0.y, x0);
                fma2(bL1, w1.x, x1); fma2(bH1, w1.y, x1);
            }
            ((float4*)s->gp)[1024 + kc2 * 32 + u2] = comb4(bL0, bH0, bL1, bH1);
        }
        __syncthreads();
        // ===== reduce + exchange (gates 512 + out 128) =====
        if (tid < 512) {
            float p = 0.f;
#pragma unroll
            for (int kc = 0; kc < 8; ++kc) p += s->gp[kc * 512 + tid];
            s->bufo[tid] = p;
            dsmem_store(&s->pc[tid], peer, p);
        } else if (tid < 640) {
            const int o = tid - 512;
            float p = 0.f;
#pragma unroll
            for (int kc = 0; kc < 32; ++kc) p += s->gp[4096 + kc * 128 + o];
            s->bufo[tid] = p;
            dsmem_store(&s->pc[tid], peer, p);
        }
        CLUSTER_SYNC();
        // out row t-1 (computed from xs of step t-1)
        if (t > 0 && rank == 0 && tid >= 512 && tid < 640)
            out[((size_t)b * Tn + (t - 1)) * Wn + (tid - 512)] =
                s->bufo[tid] + s->pc[tid] + g_bout[tid - 512];
        if (t == Tn) break;
        const int pcur = t & 1, pnxt = pcur ^ 1;
        // ctl cell: local + peer + both precomputed enc partials + bias
        if (tid < Wn) {
            const float* cp = cpre_base + (size_t)t * 1024;
            float gi = s->bufo[tid]       + s->pc[tid]       + cp[tid]       + cp[512 + tid] + g_bctl[tid];
            float gf = s->bufo[128 + tid] + s->pc[128 + tid] + cp[128 + tid] + cp[640 + tid] + g_bctl[128 + tid];
            float gg = s->bufo[256 + tid] + s->pc[256 + tid] + cp[256 + tid] + cp[768 + tid] + g_bctl[256 + tid];
            float go = s->bufo[384 + tid] + s->pc[384 + tid] + cp[384 + tid] + cp[896 + tid] + g_bctl[384 + tid];
            gi = sigm(gi); gf = sigm(gf); gg = tanhf(gg); go = sigm(go);
            float c = gf * s->c_ctl[tid] + gi * gg;
            s->c_ctl[tid] = c;
            s->xs[512 + tid] = go * tanhf(c);   // h_ctl lives in xs[512..639]
        }
        __syncthreads();

        // ===== iface GEMV: 128k (split 64) x 920j, x = h_ctl =====
        if (tid < 920) {
            const int kc = tid / 230, u = tid - kc * 230;  // 4 chunks x 16 k
            const ulonglong2* wp = ((const ulonglong2*)g_ifcT) + u;
            const float* xsrc = s->xs + 512;
            ull aL0 = 0, aH0 = 0, aL1 = 0, aH1 = 0;
            const int k0 = (int)rank * 64 + kc * 16;
#pragma unroll
            for (int kk = 0; kk < 16; kk += 4) GEMV_BLK2(wp, 230, k0 + kk);
            ((float4*)(s->gp + kc * 920))[u] = comb4(aL0, aH0, aL1, aH1);
        }
        __syncthreads();
        if (tid < 920) {
            float p = s->gp[tid] + s->gp[920 + tid] + s->gp[1840 + tid] + s->gp[2760 + tid];
            s->bufo[tid] = p;
            dsmem_store(&s->pi[tid], peer, p);
        }
        CLUSTER_SYNC();
        // ===== xi combine + parse (fused, elementwise by range) =====
        if (tid < IFACEn) {
            int j = tid;
            float v = s->bufo[j] + s->pi[j] + g_bifc[j];
            if (j < 512)       ((float*)s->rk)[j] = tanhf(v);
            else if (j < 516)  s->rstr[j - 512] = softplusf(v);
            else if (j < 644)  s->wk[j - 516] = tanhf(v);
            else if (j == 644) s->scal[0] = softplusf(v);
            else if (j < 773)  s->er[j - 645] = sigm(v);
            else if (j < 901)  s->wv[j - 773] = tanhf(v);
            else if (j < 905)  s->fg[j - 901] = sigm(v);
            else if (j == 905) s->scal[1] = sigm(v);
            else if (j == 906) s->scal[2] = sigm(v);
            else               s->xmraw[j - 907] = v;
        }
        __syncthreads();

        // ===== usage update + uu + wk norm + OLD-mem norms & wk dots =====
        if (tid < Nn) {
            float us = s->usage[tid];
            us = us + (1.f - us) * s->ww[tid];
            float ret = 1.f;
#pragma unroll
            for (int r = 0; r < Rn; ++r) ret *= (1.f - s->fg[r] * s->rw[r * Nn + tid]);
            us *= ret;
            s->usage[tid] = us;
            s->uu[tid] = DELTAf + (1.f - DELTAf) * us;
        }
        {
            float4 k4 = ((const float4*)s->wk)[lane];
            if (wid == 0) {
                float nv = wsum(dot4(k4, k4));
                if (lane == 0) s->scal[3] = sqrtf(nv);
            }
#pragma unroll
            for (int rr = 0; rr < 4; ++rr) {
                int n = wid * 4 + rr;
                float4 m4 = ((const float4*)s->mem[n])[lane];
                float dn = wsum(dot4(m4, m4));
                float dk = wsum(dot4(m4, k4));
                if (lane == 0) { s->nrm[n] = sqrtf(dn); s->wc[n] = dk; }
            }
        }
        __syncthreads();

        // ===== P1: {rank+scan (warps 0-3)} || {wc softmax (warp 8)} || {rm (warp 5)} || {rknorm (warps 12-15)} =====
        if (tid < Nn) {
            float un = s->uu[tid];
            int rk_ = 0;
#pragma unroll 8
            for (int j = 0; j < Nn; ++j) {
                float uj = s->uu[j];
                rk_ += (uj < un) || (uj == un && j < tid);
            }
            s->rnk[tid] = rk_;
            s->psu[rk_] = un;
            asm volatile("bar.sync 1, 128;" ::: "memory");
            if (wid == 0) {   // inclusive cumprod scan of psu
                float v0 = s->psu[lane * 4], v1 = s->psu[lane * 4 + 1];
                float v2 = s->psu[lane * 4 + 2], v3 = s->psu[lane * 4 + 3];
                float l1 = v0 * v1, l2 = l1 * v2, l3 = l2 * v3;
                float run = l3;
#pragma unroll
                for (int off = 1; off < 32; off <<= 1) {
                    float up = __shfl_up_sync(0xffffffffu, run, off);
                    if (lane >= off) run *= up;
                }
                float ex = __shfl_up_sync(0xffffffffu, run, 1);
                if (lane == 0) ex = 1.f;
                s->psu[lane * 4]     = ex * v0;
                s->psu[lane * 4 + 1] = ex * l1;
                s->psu[lane * 4 + 2] = ex * l2;
                s->psu[lane * 4 + 3] = ex * l3;
            }
        } else if (wid == 8) {   // write-content softmax, fully in-warp
            float inw = 1.f / ((s->scal[3] + DELTAf));
            float ws = s->scal[0];
            float v[4];
            float mx = -1e30f;
#pragma unroll
            for (int q = 0; q < 4; ++q) {
                int n = lane + 32 * q;
                v[q] = s->wc[n] / (s->nrm[n] + DELTAf) * inw * ws;
                mx = fmaxf(mx, v[q]);
            }
            mx = wmax(mx);
            float sm = 0.f;
#pragma unroll
            for (int q = 0; q < 4; ++q) { v[q] = expf(v[q] - mx); sm += v[q]; }
            sm = wsum(sm);
            float inv = 1.f / sm;
#pragma unroll
            for (int q = 0; q < 4; ++q) s->wc[lane + 32 * q] = v[q] * inv;
        } else if (wid == 5 && lane < Rn) {   // read-modes 3-way softmax
            int r = lane;
            float a = s->xmraw[r * 3], b2 = s->xmraw[r * 3 + 1], c2 = s->xmraw[r * 3 + 2];
            float m = fmaxf(a, fmaxf(b2, c2));
            float ea = expf(a - m), eb = expf(b2 - m), ec = expf(c2 - m);
            float inv = 1.f / (ea + eb + ec);
            s->rm[r][0] = ea * inv; s->rm[r][1] = eb * inv; s->rm[r][2] = ec * inv;
        } else if (wid >= 12 && wid < 12 + Rn) {   // read-key norms
            int r = wid - 12;
            float4 k4 = ((const float4*)s->rk[r])[lane];
            float nv = wsum(dot4(k4, k4));
            if (lane == 0) s->rknorm[r] = sqrtf(nv);
        }
        __syncthreads();

        // ===== P3: alloc + new write weighting + warp partial sums =====
        if (tid < Nn) {
            int r_ = s->rnk[tid];
            float excl = (r_ == 0) ? 1.f : s->psu[r_ - 1];
            float alloc = (1.f - s->uu[tid]) * excl;
            float ag = s->scal[1], wg = s->scal[2];
            float v = wg * (ag * alloc + (1.f - ag) * s->wc[tid]);
            s->ww[tid] = v;
            float sm = wsum(v);
            if (lane == 0) s->red[wid] = sm;
        }
        __syncthreads();

        // ===== P4: mem erase+write FUSED with new-mem dots; link update; prec =====
        {
            float4 k0 = ((const float4*)s->rk[0])[lane];
            float4 k1 = ((const float4*)s->rk[1])[lane];
            float4 k2 = ((const float4*)s->rk[2])[lane];
            float4 k3 = ((const float4*)s->rk[3])[lane];
            float4* m4 = (float4*)s->mem;
            const float4* e4p = (const float4*)s->er;
            const float4* v4p = (const float4*)s->wv;
            float4 e = e4p[lane], v = v4p[lane];
#pragma unroll
            for (int it = 0; it < 4; ++it) {
                int idx = tid + it * NTH;
                int n = wid + it * 32;           // (idx>>5) == wid + 32*it; (idx&31)==lane
                float wwn = s->ww[n];
                float4 m = m4[idx];
                m.x = m.x * (1.f - wwn * e.x) + wwn * v.x;
                m.y = m.y * (1.f - wwn * e.y) + wwn * v.y;
                m.z = m.z * (1.f - wwn * e.z) + wwn * v.z;
                m.w = m.w * (1.f - wwn * e.w) + wwn * v.w;
                m4[idx] = m;
                // fused new-mem dots (row already in registers)
                float dn = wsum(dot4(m, m));
                float d0 = wsum(dot4(m, k0));
                float d1 = wsum(dot4(m, k1));
                float d2 = wsum(dot4(m, k2));
                float d3 = wsum(dot4(m, k3));
                if (lane == 0) {
                    s->nrm[n] = sqrtf(dn);
                    s->rc[0][n] = d0; s->rc[1][n] = d1; s->rc[2][n] = d2; s->rc[3][n] = d3;
                }
            }
            float4* l4 = (float4*)s->lnk;
            const float4* wwp = (const float4*)s->ww;
            const float4* pcp = (const float4*)s->prec[pcur];
#pragma unroll
            for (int it = 0; it < 4; ++it) {
                int idx = tid + it * NTH;
                int i = idx >> 5, q = idx & 31;
                float wwi = s->ww[i];
                float4 L = l4[idx], wj = wwp[q], pj = pcp[q];
                L.x = (1.f - wwi - wj.x) * L.x + wwi * pj.x;
                L.y = (1.f - wwi - wj.y) * L.y + wwi * pj.y;
                L.z = (1.f - wwi - wj.z) * L.z + wwi * pj.z;
                L.w = (1.f - wwi - wj.w) * L.w + wwi * pj.w;
                if ((i >> 2) == q) ((float*)&L)[i & 3] = 0.f;
                l4[idx] = L;
            }
            if (wid == 31) {
                float vv = (lane < 4) ? s->red[lane] : 0.f;
                float sw = wsum(vv);
#pragma unroll
                for (int q = 0; q < 4; ++q) {
                    int n = lane + 32 * q;
                    s->prec[pnxt][n] = (1.f - sw) * s->prec[pcur][n] + s->ww[n];
                }
            }
        }
        __syncthreads();

        // ===== P6: {read softmax (warps 0-3, in-warp)} || {fw row-dots (warps 4-31)} =====
        if (wid < Rn) {
            int r_ = wid;
            float inv_kn = 1.f / (s->rknorm[r_] + DELTAf);
            float rs = s->rstr[r_];
            float v[4];
            float mx = -1e30f;
#pragma unroll
            for (int q = 0; q < 4; ++q) {
                int n = lane + 32 * q;
                v[q] = s->rc[r_][n] / (s->nrm[n] + DELTAf) * inv_kn * rs;
                mx = fmaxf(mx, v[q]);
            }
            mx = wmax(mx);
            float sm = 0.f;
#pragma unroll
            for (int q = 0; q < 4; ++q) { v[q] = expf(v[q] - mx); sm += v[q]; }
            sm = wsum(sm);
            float inv = 1.f / sm;
#pragma unroll
            for (int q = 0; q < 4; ++q) s->rc[r_][lane + 32 * q] = v[q] * inv;
        } else {
            float4 w0 = ((const float4*)s->rw)[lane];
            float4 w1 = ((const float4*)s->rw)[32 + lane];
            float4 w2 = ((const float4*)s->rw)[64 + lane];
            float4 w3 = ((const float4*)s->rw)[96 + lane];
            for (int i = wid - 4; i < Nn; i += 28) {
                float4 L = ((const float4*)s->lnk[i])[lane];
                float d0 = wsum(dot4(L, w0));
                float d1 = wsum(dot4(L, w1));
                float d2 = wsum(dot4(L, w2));
                float d3 = wsum(dot4(L, w3));
                if (lane == 0) {
                    s->fwv[0][i] = d0; s->fwv[1][i] = d1;
                    s->fwv[2][i] = d2; s->fwv[3][i] = d3;
                }
            }
        }
        __syncthreads();

        // ===== P7a: bw partial dots, float4-vectorized, 4-way j-split =====
        if (tid < 512) {
            const int r_ = tid >> 7, q = tid & 127;
            const int i4 = q & 31, js = q >> 5;
            const float* rwr = s->rw + r_ * Nn;
            const ulonglong2* L2 = (const ulonglong2*)s->lnk;
            ull aL = 0, aH = 0;
            const int j0 = js * 32;
#pragma unroll 8
            for (int j = j0; j < j0 + 32; ++j) {
                ull f = packf2(rwr[j]);
                ulonglong2 lw = L2[(size_t)j * 32 + i4];
                fma2(aL, lw.x, f); fma2(aH, lw.y, f);
            }
            float2 lo = unpackf2(aL), hi = unpackf2(aH);
            ((float4*)s->gp)[tid] = make_float4(lo.x, lo.y, hi.x, hi.y);
        }
        __syncthreads();
        // ===== P7b: combine bw + read modes -> rwn; commit rw =====
        if (tid < 512) {
            const int r_ = tid >> 7, i = tid & 127;
            float bw = s->gp[r_ * 512 + i] + s->gp[r_ * 512 + 128 + i]
                     + s->gp[r_ * 512 + 256 + i] + s->gp[r_ * 512 + 384 + i];
            float val = s->rm[r_][0] * bw
                      + s->rm[r_][1] * s->fwv[r_][i]
                      + s->rm[r_][2] * s->rc[r_][i];
            s->rwn[tid] = val;
            s->rw[tid] = val;
        }
        __syncthreads();

        // ===== P8a: rv partial dots, float4-vectorized, 4-way n-split =====
        if (tid < 512) {
            const int r_ = tid >> 7, q = tid & 127;
            const int w4 = q & 31, js = q >> 5;
            const float* rwn_r = s->rwn + r_ * Nn;
            const ulonglong2* M2 = (const ulonglong2*)s->mem;
            ull aL = 0, aH = 0;
            const int n0 = js * 32;
#pragma unroll 8
            for (int n = n0; n < n0 + 32; ++n) {
                ull f = packf2(rwn_r[n]);
                ulonglong2 mw = M2[(size_t)n * 32 + w4];
                fma2(aL, mw.x, f); fma2(aH, mw.y, f);
            }
            float2 lo = unpackf2(aL), hi = unpackf2(aH);
            ((float4*)s->gp)[tid] = make_float4(lo.x, lo.y, hi.x, hi.y);
        }
        __syncthreads();
        // ===== P8b: combine -> xs[rv] =====
        if (tid < 512) {
            const int r_ = tid >> 7, w = tid & 127;
            float val = s->gp[r_ * 512 + w] + s->gp[r_ * 512 + 128 + w]
                      + s->gp[r_ * 512 + 256 + w] + s->gp[r_ * 512 + 384 + w];
            s->xs[w * 4 + r_] = val;
        }
        __syncthreads();
    }
}

extern "C" void kernel_launch(void* const* d_in, const int* in_sizes, int n_in,
                              void* d_out, int out_size) {
    const float* input   = (const float*)d_in[0];
    // d_in[1] = source_lengths (all == T, unused)
    const float* enc_Wih = (const float*)d_in[2];
    const float* enc_Whh = (const float*)d_in[3];
    const float* enc_bih = (const float*)d_in[4];
    const float* enc_bhh = (const float*)d_in[5];
    const float* ctl_Wih = (const float*)d_in[6];
    const float* ctl_Whh = (const float*)d_in[7];
    const float* ctl_bih = (const float*)d_in[8];
    const float* ctl_bhh = (const float*)d_in[9];
    const float* iface_W = (const float*)d_in[10];
    const float* iface_b = (const float*)d_in[11];
    const float* out_W   = (const float*)d_in[12];
    const float* out_b   = (const float*)d_in[13];
    float* out = (float*)d_out;

    prep_kernel<<<448, 256>>>(enc_Wih, enc_Whh, enc_bih, enc_bhh,
                              ctl_Wih, ctl_Whh, ctl_bih, ctl_bhh,
                              iface_W, iface_b, out_W, out_b);

    int esm = (int)sizeof(EncSmem);
    cudaFuncSetAttribute(enc_kernel, cudaFuncAttributeMaxDynamicSharedMemorySize, esm);
    enc_kernel<<<2 * Bn, NTH, esm>>>(input);

    int smem = (int)sizeof(Smem);
    cudaFuncSetAttribute(dnc_kernel, cudaFuncAttributeMaxDynamicSharedMemorySize, smem);
    dnc_kernel<<<2 * Bn, NTH, smem>>>(out);
}